// round 1
// baseline (speedup 1.0000x reference)
#include <cuda_runtime.h>
#include <math.h>

#define N_NODES 50000
#define N_EDGES 800000
#define NFEAT 512
#define NHID 128
#define NCLASS 40

// ---- scratch (static device arrays; no allocation allowed) ----
__device__ float g_S[(size_t)N_NODES * 256];     // [xW1 | xWr1+br1]
__device__ float g_agg1[(size_t)N_NODES * 128];  // b1 + spmm(xW1)
__device__ float g_h[(size_t)N_NODES * 256];     // [relu(gc1) | xWr1+br1]
__device__ float g_T[(size_t)N_NODES * 80];      // [hW2 | hWr2+br2]
__device__ float g_agg2[(size_t)N_NODES * 40];   // b2 + spmm(hW2)
__device__ float g_Wc1[NFEAT * 256];             // [W1 | Wr1]
__device__ float g_Wc2[256 * 80];                // [W2 | Wr2]
__device__ float g_bc1[256];                     // [0...0 | br1]
__device__ float g_bc2[80];                      // [0...0 | br2]

// ---- pack weights + epilogue biases ----
__global__ void pack_kernel(const float* __restrict__ W1, const float* __restrict__ Wr1,
                            const float* __restrict__ br1,
                            const float* __restrict__ W2, const float* __restrict__ Wr2,
                            const float* __restrict__ br2) {
    int idx = blockIdx.x * blockDim.x + threadIdx.x;
    if (idx < NFEAT * 256) {
        int k = idx >> 8, j = idx & 255;
        g_Wc1[idx] = (j < 128) ? W1[k * 128 + j] : Wr1[k * 128 + (j - 128)];
    }
    if (idx < 256 * 80) {
        int k = idx / 80, j = idx % 80;
        g_Wc2[idx] = (j < 40) ? W2[k * 40 + j] : Wr2[k * 40 + (j - 40)];
    }
    if (idx < 256) g_bc1[idx] = (idx < 128) ? 0.f : br1[idx - 128];
    if (idx < 80)  g_bc2[idx] = (idx < 40) ? 0.f : br2[idx - 40];
}

// ---- init aggregates with the GCN biases ----
__global__ void init_agg_kernel(const float* __restrict__ b1, const float* __restrict__ b2) {
    long idx = (long)blockIdx.x * blockDim.x + threadIdx.x;
    if (idx < (long)N_NODES * 128) g_agg1[idx] = b1[idx & 127];
    if (idx < (long)N_NODES * 40)  g_agg2[idx] = b2[idx % 40];
}

// ---- classic fp32 SGEMM: C[M,N] = A[M,K] @ B[K,N] + bias[N] ----
// BM=BN=64, BK=16, 256 threads, 4x4 per thread
__global__ __launch_bounds__(256) void sgemm64(const float* __restrict__ A,
                                               const float* __restrict__ B,
                                               const float* __restrict__ bias,
                                               float* __restrict__ C,
                                               int M, int N, int K) {
    __shared__ float As[16][68];  // transposed: As[k][row]
    __shared__ float Bs[16][68];  // Bs[k][col]

    int tid = threadIdx.x;
    int tx = tid & 15, ty = tid >> 4;
    int block_row = blockIdx.x * 64;
    int block_col = blockIdx.y * 64;

    int a_row = tid >> 2;         // 0..63
    int a_col = (tid & 3) * 4;    // 0,4,8,12
    int b_row = tid >> 4;         // 0..15
    int b_col = (tid & 15) * 4;   // 0..60

    float acc[4][4] = {};

    for (int k0 = 0; k0 < K; k0 += 16) {
        float4 av = make_float4(0.f, 0.f, 0.f, 0.f);
        int gr = block_row + a_row;
        if (gr < M) av = *(const float4*)&A[(long)gr * K + k0 + a_col];
        As[a_col + 0][a_row] = av.x;
        As[a_col + 1][a_row] = av.y;
        As[a_col + 2][a_row] = av.z;
        As[a_col + 3][a_row] = av.w;

        float4 bv = make_float4(0.f, 0.f, 0.f, 0.f);
        int gc = block_col + b_col;
        if (gc + 3 < N) bv = *(const float4*)&B[(long)(k0 + b_row) * N + gc];
        *(float4*)&Bs[b_row][b_col] = bv;

        __syncthreads();
#pragma unroll
        for (int k = 0; k < 16; k++) {
            float4 a = *(const float4*)&As[k][ty * 4];
            float4 b = *(const float4*)&Bs[k][tx * 4];
            acc[0][0] += a.x * b.x; acc[0][1] += a.x * b.y; acc[0][2] += a.x * b.z; acc[0][3] += a.x * b.w;
            acc[1][0] += a.y * b.x; acc[1][1] += a.y * b.y; acc[1][2] += a.y * b.z; acc[1][3] += a.y * b.w;
            acc[2][0] += a.z * b.x; acc[2][1] += a.z * b.y; acc[2][2] += a.z * b.z; acc[2][3] += a.z * b.w;
            acc[3][0] += a.w * b.x; acc[3][1] += a.w * b.y; acc[3][2] += a.w * b.z; acc[3][3] += a.w * b.w;
        }
        __syncthreads();
    }

#pragma unroll
    for (int i = 0; i < 4; i++) {
        int r = block_row + ty * 4 + i;
        if (r >= M) continue;
#pragma unroll
        for (int j = 0; j < 4; j++) {
            int c = block_col + tx * 4 + j;
            if (c < N) C[(long)r * N + c] = acc[i][j] + bias[c];
        }
    }
}

// ---- SpMM1: warp per edge, 128 features (float4 per lane) ----
__global__ void spmm1_kernel(const int* __restrict__ src, const int* __restrict__ dst,
                             const float* __restrict__ val) {
    int warp = (blockIdx.x * blockDim.x + threadIdx.x) >> 5;
    int lane = threadIdx.x & 31;
    if (warp >= N_EDGES) return;
    int s = src[warp];
    int d = dst[warp];
    float v = val[warp];
    float4 sv = *(const float4*)&g_S[(long)s * 256 + lane * 4];  // support1 = S[:, :128]
    float* o = &g_agg1[(long)d * 128 + lane * 4];
    atomicAdd(o + 0, v * sv.x);
    atomicAdd(o + 1, v * sv.y);
    atomicAdd(o + 2, v * sv.z);
    atomicAdd(o + 3, v * sv.w);
}

// ---- build h = [relu(agg1) | S[:,128:]] ----
__global__ void build_h_kernel() {
    long idx = (long)blockIdx.x * blockDim.x + threadIdx.x;
    if (idx >= (long)N_NODES * 256) return;
    int c = (int)(idx & 255);
    long row = idx >> 8;
    float x;
    if (c < 128) x = fmaxf(g_agg1[row * 128 + c], 0.f);
    else         x = g_S[idx];
    g_h[idx] = x;
}

// ---- SpMM2: thread per (edge, class) ----
__global__ void spmm2_kernel(const int* __restrict__ src, const int* __restrict__ dst,
                             const float* __restrict__ val) {
    long idx = (long)blockIdx.x * blockDim.x + threadIdx.x;
    if (idx >= (long)N_EDGES * 40) return;
    int e = (int)(idx / 40);
    int f = (int)(idx % 40);
    int s = src[e];
    int d = dst[e];
    atomicAdd(&g_agg2[(long)d * 40 + f], val[e] * g_T[(long)s * 80 + f]);  // support2 = T[:, :40]
}

// ---- final: h2 = agg2 + T[:,40:]; log_softmax; warp per row ----
__global__ void final_kernel(float* __restrict__ out) {
    int row = (blockIdx.x * blockDim.x + threadIdx.x) >> 5;
    int lane = threadIdx.x & 31;
    if (row >= N_NODES) return;

    float v0 = g_agg2[(long)row * 40 + lane < (long)N_NODES * 40 ? (long)row * 40 + lane : 0];
    v0 = (lane < 40) ? g_agg2[(long)row * 40 + lane] + g_T[(long)row * 80 + 40 + lane] : -1e30f;
    // lanes 0..31 handle cols 0..31; lanes 0..7 also handle cols 32..39
    float v1 = (lane < 8) ? g_agg2[(long)row * 40 + 32 + lane] + g_T[(long)row * 80 + 72 + lane] : -1e30f;

    float m = fmaxf(v0, v1);
#pragma unroll
    for (int o = 16; o > 0; o >>= 1) m = fmaxf(m, __shfl_xor_sync(0xffffffffu, m, o));

    float s = __expf(v0 - m) + ((lane < 8) ? __expf(v1 - m) : 0.f);
#pragma unroll
    for (int o = 16; o > 0; o >>= 1) s += __shfl_xor_sync(0xffffffffu, s, o);

    float lse = logf(s);
    out[(long)row * 40 + lane] = v0 - m - lse;
    if (lane < 8) out[(long)row * 40 + 32 + lane] = v1 - m - lse;
}

extern "C" void kernel_launch(void* const* d_in, const int* in_sizes, int n_in,
                              void* d_out, int out_size) {
    const float* x    = (const float*)d_in[0];
    const int*   esrc = (const int*)d_in[1];
    const int*   edst = (const int*)d_in[2];
    const float* eval_= (const float*)d_in[3];
    const float* W1   = (const float*)d_in[4];
    const float* b1   = (const float*)d_in[5];
    const float* Wr1  = (const float*)d_in[6];
    const float* br1  = (const float*)d_in[7];
    const float* W2   = (const float*)d_in[8];
    const float* b2   = (const float*)d_in[9];
    const float* Wr2  = (const float*)d_in[10];
    const float* br2  = (const float*)d_in[11];
    float* out = (float*)d_out;

    void *pS, *pH, *pT, *pWc1, *pWc2, *pBc1, *pBc2;
    cudaGetSymbolAddress(&pS, g_S);
    cudaGetSymbolAddress(&pH, g_h);
    cudaGetSymbolAddress(&pT, g_T);
    cudaGetSymbolAddress(&pWc1, g_Wc1);
    cudaGetSymbolAddress(&pWc2, g_Wc2);
    cudaGetSymbolAddress(&pBc1, g_bc1);
    cudaGetSymbolAddress(&pBc2, g_bc2);

    // 1. pack weights / biases
    pack_kernel<<<(NFEAT * 256 + 255) / 256, 256>>>(W1, Wr1, br1, W2, Wr2, br2);

    // 2. init aggregates with biases
    init_agg_kernel<<<((long)N_NODES * 128 + 255) / 256, 256>>>(b1, b2);

    // 3. S = x @ [W1|Wr1] (+[0|br1])
    {
        dim3 grid((N_NODES + 63) / 64, (256 + 63) / 64);
        sgemm64<<<grid, 256>>>(x, (const float*)pWc1, (const float*)pBc1,
                               (float*)pS, N_NODES, 256, NFEAT);
    }

    // 4. agg1 += spmm(S[:, :128])
    spmm1_kernel<<<(N_EDGES * 32 + 255) / 256, 256>>>(esrc, edst, eval_);

    // 5. h = [relu(agg1) | S[:,128:]]
    build_h_kernel<<<((long)N_NODES * 256 + 255) / 256, 256>>>();

    // 6. T = h @ [W2|Wr2] (+[0|br2])
    {
        dim3 grid((N_NODES + 63) / 64, (80 + 63) / 64);
        sgemm64<<<grid, 256>>>((const float*)pH, (const float*)pWc2, (const float*)pBc2,
                               (float*)pT, N_NODES, 80, 256);
    }

    // 7. agg2 += spmm(T[:, :40])
    spmm2_kernel<<<((long)N_EDGES * 40 + 255) / 256, 256>>>(esrc, edst, eval_);

    // 8. h2 = agg2 + T[:,40:]; log_softmax -> out
    final_kernel<<<(N_NODES * 32 + 255) / 256, 256>>>(out);
}

// round 2
// speedup vs baseline: 1.5150x; 1.5150x over previous
#include <cuda_runtime.h>
#include <math.h>

#define N_NODES 50000
#define N_EDGES 800000
#define NFEAT 512
#define NHID 128
#define NCLASS 40

// ---- scratch (static device arrays; no allocation allowed) ----
__device__ float g_S[(size_t)N_NODES * 256];     // [xW1 | xWr1+br1]
__device__ float g_h[(size_t)N_NODES * 256];     // [relu(gc1) | xWr1+br1]
__device__ float g_T[(size_t)N_NODES * 80];      // [hW2 | hWr2+br2]
__device__ float g_Wc1[NFEAT * 256];             // [W1 | Wr1]
__device__ float g_Wc2[256 * 80];                // [W2 | Wr2]
__device__ float g_bc1[256];                     // [0 | br1]
__device__ float g_bc2[80];                      // [0 | br2]
// CSR-by-destination build
__device__ int   g_counts[N_NODES];
__device__ int   g_row_start[N_NODES + 1];
__device__ int   g_cursor[N_NODES];
__device__ int   g_es[N_EDGES];                  // src, sorted by dst
__device__ float g_ev[N_EDGES];                  // val, sorted by dst

// ---- pack weights + epilogue biases + zero histogram ----
__global__ void pack_kernel(const float* __restrict__ W1, const float* __restrict__ Wr1,
                            const float* __restrict__ br1,
                            const float* __restrict__ W2, const float* __restrict__ Wr2,
                            const float* __restrict__ br2) {
    int idx = blockIdx.x * blockDim.x + threadIdx.x;
    if (idx < NFEAT * 256) {
        int k = idx >> 8, j = idx & 255;
        g_Wc1[idx] = (j < 128) ? W1[k * 128 + j] : Wr1[k * 128 + (j - 128)];
    }
    if (idx < 256 * 80) {
        int k = idx / 80, j = idx % 80;
        g_Wc2[idx] = (j < 40) ? W2[k * 40 + j] : Wr2[k * 40 + (j - 40)];
    }
    if (idx < 256) g_bc1[idx] = (idx < 128) ? 0.f : br1[idx - 128];
    if (idx < 80)  g_bc2[idx] = (idx < 40) ? 0.f : br2[idx - 40];
    if (idx < N_NODES) g_counts[idx] = 0;
}

// ---- histogram of destination degrees ----
__global__ void hist_kernel(const int* __restrict__ dst) {
    int e = blockIdx.x * blockDim.x + threadIdx.x;
    if (e < N_EDGES) atomicAdd(&g_counts[dst[e]], 1);
}

// ---- single-block exclusive scan of counts -> row_start, cursor ----
__global__ void scan_kernel() {
    __shared__ int buf[2][1024];
    int tid = threadIdx.x;
    int offset = 0;
    for (int base = 0; base < N_NODES; base += 1024) {
        int i = base + tid;
        int c = (i < N_NODES) ? g_counts[i] : 0;
        int cur = 0;
        buf[0][tid] = c;
        __syncthreads();
#pragma unroll
        for (int d = 1; d < 1024; d <<= 1) {
            int v = buf[cur][tid];
            if (tid >= d) v += buf[cur][tid - d];
            buf[1 - cur][tid] = v;
            cur ^= 1;
            __syncthreads();
        }
        int incl = buf[cur][tid];
        int tot  = buf[cur][1023];
        if (i < N_NODES) {
            int ex = offset + incl - c;
            g_row_start[i] = ex;
            g_cursor[i] = ex;
        }
        offset += tot;
        __syncthreads();
    }
    if (tid == 0) g_row_start[N_NODES] = offset;
}

// ---- scatter edges into CSR order ----
__global__ void scatter_kernel(const int* __restrict__ src, const int* __restrict__ dst,
                               const float* __restrict__ val) {
    int e = blockIdx.x * blockDim.x + threadIdx.x;
    if (e >= N_EDGES) return;
    int d = dst[e];
    int p = atomicAdd(&g_cursor[d], 1);
    g_es[p] = src[e];
    g_ev[p] = val[e];
}

// ---- SGEMM 128x128x16 fp32, bias epilogue: C = A @ B + bias ----
__global__ __launch_bounds__(256) void sgemm128(const float* __restrict__ A,
                                                const float* __restrict__ B,
                                                const float* __restrict__ bias,
                                                float* __restrict__ C,
                                                int M, int N, int K) {
    __shared__ float As[16][132];
    __shared__ float Bs[16][128];
    int tid = threadIdx.x;
    int brow = blockIdx.x * 128, bcol = blockIdx.y * 128;
    int ar0 = tid >> 2;            // 0..63 (+64)
    int ak  = (tid & 3) * 4;       // 0,4,8,12
    int br0 = tid >> 5;            // 0..7 (+8)
    int bc  = (tid & 31) * 4;      // 0..124
    int tx = tid & 15, ty = tid >> 4;

    float acc[8][8] = {};

    for (int k0 = 0; k0 < K; k0 += 16) {
#pragma unroll
        for (int h = 0; h < 2; h++) {
            int r = brow + ar0 + h * 64;
            float4 v = make_float4(0.f, 0.f, 0.f, 0.f);
            if (r < M) v = *(const float4*)&A[(long)r * K + k0 + ak];
            As[ak + 0][ar0 + h * 64] = v.x;
            As[ak + 1][ar0 + h * 64] = v.y;
            As[ak + 2][ar0 + h * 64] = v.z;
            As[ak + 3][ar0 + h * 64] = v.w;
        }
#pragma unroll
        for (int h = 0; h < 2; h++) {
            int kr = k0 + br0 + h * 8;
            int c = bcol + bc;
            float4 v = make_float4(0.f, 0.f, 0.f, 0.f);
            if (c + 3 < N) v = *(const float4*)&B[(long)kr * N + c];
            *(float4*)&Bs[br0 + h * 8][bc] = v;
        }
        __syncthreads();
#pragma unroll
        for (int k = 0; k < 16; k++) {
            float a[8], b[8];
            *(float4*)&a[0] = *(const float4*)&As[k][ty * 8];
            *(float4*)&a[4] = *(const float4*)&As[k][ty * 8 + 4];
            *(float4*)&b[0] = *(const float4*)&Bs[k][tx * 8];
            *(float4*)&b[4] = *(const float4*)&Bs[k][tx * 8 + 4];
#pragma unroll
            for (int i = 0; i < 8; i++)
#pragma unroll
                for (int j = 0; j < 8; j++)
                    acc[i][j] = fmaf(a[i], b[j], acc[i][j]);
        }
        __syncthreads();
    }

#pragma unroll
    for (int i = 0; i < 8; i++) {
        int r = brow + ty * 8 + i;
        if (r >= M) continue;
#pragma unroll
        for (int j4 = 0; j4 < 8; j4 += 4) {
            int c = bcol + tx * 8 + j4;
            if (c + 3 >= N) continue;
            float4 o;
            o.x = acc[i][j4 + 0] + bias[c + 0];
            o.y = acc[i][j4 + 1] + bias[c + 1];
            o.z = acc[i][j4 + 2] + bias[c + 2];
            o.w = acc[i][j4 + 3] + bias[c + 3];
            *(float4*)&C[(long)r * N + c] = o;
        }
    }
}

// ---- SGEMM 128x80x16: C[M,80] = A[M,256] @ B[256,80] + bias (exact N=80) ----
__global__ __launch_bounds__(256) void sgemm_n80(const float* __restrict__ A,
                                                 const float* __restrict__ B,
                                                 const float* __restrict__ bias,
                                                 float* __restrict__ C,
                                                 int M, int K) {
    __shared__ float As[16][132];
    __shared__ float Bs[16][80];
    int tid = threadIdx.x;
    int brow = blockIdx.x * 128;
    int ar0 = tid >> 2;
    int ak  = (tid & 3) * 4;
    int tx = tid & 15, ty = tid >> 4;   // col = tx*5, row = ty*8

    float acc[8][5] = {};

    for (int k0 = 0; k0 < K; k0 += 16) {
#pragma unroll
        for (int h = 0; h < 2; h++) {
            int r = brow + ar0 + h * 64;
            float4 v = make_float4(0.f, 0.f, 0.f, 0.f);
            if (r < M) v = *(const float4*)&A[(long)r * K + k0 + ak];
            As[ak + 0][ar0 + h * 64] = v.x;
            As[ak + 1][ar0 + h * 64] = v.y;
            As[ak + 2][ar0 + h * 64] = v.z;
            As[ak + 3][ar0 + h * 64] = v.w;
        }
        // B tile: 16x80 = 1280 floats, 5 scalar loads per thread
#pragma unroll
        for (int h = 0; h < 5; h++) {
            int idx = h * 256 + tid;
            int kr = idx / 80, c = idx - kr * 80;
            Bs[kr][c] = B[(long)(k0 + kr) * 80 + c];
        }
        __syncthreads();
#pragma unroll
        for (int k = 0; k < 16; k++) {
            float a[8], b[5];
            *(float4*)&a[0] = *(const float4*)&As[k][ty * 8];
            *(float4*)&a[4] = *(const float4*)&As[k][ty * 8 + 4];
#pragma unroll
            for (int j = 0; j < 5; j++) b[j] = Bs[k][tx * 5 + j];
#pragma unroll
            for (int i = 0; i < 8; i++)
#pragma unroll
                for (int j = 0; j < 5; j++)
                    acc[i][j] = fmaf(a[i], b[j], acc[i][j]);
        }
        __syncthreads();
    }

#pragma unroll
    for (int i = 0; i < 8; i++) {
        int r = brow + ty * 8 + i;
        if (r >= M) continue;
#pragma unroll
        for (int j = 0; j < 5; j++) {
            int c = tx * 5 + j;
            C[(long)r * 80 + c] = acc[i][j] + bias[c];
        }
    }
}

// ---- SpMM1 (CSR, warp per dst row) fused: bias + relu + residual copy -> h ----
__global__ void spmm1_csr(const float* __restrict__ b1) {
    int w = (blockIdx.x * blockDim.x + threadIdx.x) >> 5;
    int lane = threadIdx.x & 31;
    if (w >= N_NODES) return;
    int e = g_row_start[w];
    int end = g_row_start[w + 1];
    float4 acc = *(const float4*)&b1[lane * 4];
    for (; e + 2 <= end; e += 2) {
        int s0 = g_es[e], s1 = g_es[e + 1];
        float v0 = g_ev[e], v1 = g_ev[e + 1];
        float4 x0 = *(const float4*)&g_S[(long)s0 * 256 + lane * 4];
        float4 x1 = *(const float4*)&g_S[(long)s1 * 256 + lane * 4];
        acc.x = fmaf(v0, x0.x, acc.x); acc.y = fmaf(v0, x0.y, acc.y);
        acc.z = fmaf(v0, x0.z, acc.z); acc.w = fmaf(v0, x0.w, acc.w);
        acc.x = fmaf(v1, x1.x, acc.x); acc.y = fmaf(v1, x1.y, acc.y);
        acc.z = fmaf(v1, x1.z, acc.z); acc.w = fmaf(v1, x1.w, acc.w);
    }
    if (e < end) {
        int s0 = g_es[e];
        float v0 = g_ev[e];
        float4 x0 = *(const float4*)&g_S[(long)s0 * 256 + lane * 4];
        acc.x = fmaf(v0, x0.x, acc.x); acc.y = fmaf(v0, x0.y, acc.y);
        acc.z = fmaf(v0, x0.z, acc.z); acc.w = fmaf(v0, x0.w, acc.w);
    }
    float4 o;
    o.x = fmaxf(acc.x, 0.f); o.y = fmaxf(acc.y, 0.f);
    o.z = fmaxf(acc.z, 0.f); o.w = fmaxf(acc.w, 0.f);
    *(float4*)&g_h[(long)w * 256 + lane * 4] = o;
    float4 r = *(const float4*)&g_S[(long)w * 256 + 128 + lane * 4];
    *(float4*)&g_h[(long)w * 256 + 128 + lane * 4] = r;
}

// ---- SpMM2 (CSR, warp per dst row) fused: bias + residual + log_softmax -> out ----
__global__ void spmm2_final(const float* __restrict__ b2, float* __restrict__ out) {
    int w = (blockIdx.x * blockDim.x + threadIdx.x) >> 5;
    int lane = threadIdx.x & 31;
    if (w >= N_NODES) return;
    int e = g_row_start[w];
    int end = g_row_start[w + 1];
    bool act = lane < 20;
    float ax = 0.f, ay = 0.f;
    if (act) { ax = b2[2 * lane]; ay = b2[2 * lane + 1]; }
    for (; e + 2 <= end; e += 2) {
        int s0 = g_es[e], s1 = g_es[e + 1];
        float v0 = g_ev[e], v1 = g_ev[e + 1];
        if (act) {
            float2 t0 = *(const float2*)&g_T[(long)s0 * 80 + 2 * lane];
            float2 t1 = *(const float2*)&g_T[(long)s1 * 80 + 2 * lane];
            ax = fmaf(v0, t0.x, ax); ay = fmaf(v0, t0.y, ay);
            ax = fmaf(v1, t1.x, ax); ay = fmaf(v1, t1.y, ay);
        }
    }
    if (e < end) {
        int s0 = g_es[e];
        float v0 = g_ev[e];
        if (act) {
            float2 t0 = *(const float2*)&g_T[(long)s0 * 80 + 2 * lane];
            ax = fmaf(v0, t0.x, ax); ay = fmaf(v0, t0.y, ay);
        }
    }
    if (act) {
        float2 r = *(const float2*)&g_T[(long)w * 80 + 40 + 2 * lane];
        ax += r.x; ay += r.y;
    }
    float m = act ? fmaxf(ax, ay) : -INFINITY;
#pragma unroll
    for (int o = 16; o > 0; o >>= 1) m = fmaxf(m, __shfl_xor_sync(0xffffffffu, m, o));
    float s = act ? (__expf(ax - m) + __expf(ay - m)) : 0.f;
#pragma unroll
    for (int o = 16; o > 0; o >>= 1) s += __shfl_xor_sync(0xffffffffu, s, o);
    float lse = m + logf(s);
    if (act) {
        out[(long)w * 40 + 2 * lane + 0] = ax - lse;
        out[(long)w * 40 + 2 * lane + 1] = ay - lse;
    }
}

extern "C" void kernel_launch(void* const* d_in, const int* in_sizes, int n_in,
                              void* d_out, int out_size) {
    const float* x    = (const float*)d_in[0];
    const int*   esrc = (const int*)d_in[1];
    const int*   edst = (const int*)d_in[2];
    const float* eval_= (const float*)d_in[3];
    const float* W1   = (const float*)d_in[4];
    const float* b1   = (const float*)d_in[5];
    const float* Wr1  = (const float*)d_in[6];
    const float* br1  = (const float*)d_in[7];
    const float* W2   = (const float*)d_in[8];
    const float* b2   = (const float*)d_in[9];
    const float* Wr2  = (const float*)d_in[10];
    const float* br2  = (const float*)d_in[11];
    float* out = (float*)d_out;

    void *pS, *pH, *pT, *pWc1, *pWc2, *pBc1, *pBc2;
    cudaGetSymbolAddress(&pS, g_S);
    cudaGetSymbolAddress(&pH, g_h);
    cudaGetSymbolAddress(&pT, g_T);
    cudaGetSymbolAddress(&pWc1, g_Wc1);
    cudaGetSymbolAddress(&pWc2, g_Wc2);
    cudaGetSymbolAddress(&pBc1, g_bc1);
    cudaGetSymbolAddress(&pBc2, g_bc2);

    // 1. pack weights / biases, zero histogram
    pack_kernel<<<(NFEAT * 256 + 255) / 256, 256>>>(W1, Wr1, br1, W2, Wr2, br2);

    // 2-4. CSR build (by destination)
    hist_kernel<<<(N_EDGES + 255) / 256, 256>>>(edst);
    scan_kernel<<<1, 1024>>>();
    scatter_kernel<<<(N_EDGES + 255) / 256, 256>>>(esrc, edst, eval_);

    // 5. S = x @ [W1|Wr1] (+[0|br1])
    {
        dim3 grid((N_NODES + 127) / 128, 2);
        sgemm128<<<grid, 256>>>(x, (const float*)pWc1, (const float*)pBc1,
                                (float*)pS, N_NODES, 256, NFEAT);
    }

    // 6. h = [relu(b1 + spmm(S[:,:128])) | S[:,128:]]
    spmm1_csr<<<(N_NODES + 7) / 8, 256>>>(b1);

    // 7. T = h @ [W2|Wr2] (+[0|br2])
    sgemm_n80<<<(N_NODES + 127) / 128, 256>>>((const float*)pH, (const float*)pWc2,
                                              (const float*)pBc2, (float*)pT,
                                              N_NODES, 256);

    // 8. out = log_softmax(b2 + spmm(T[:,:40]) + T[:,40:])
    spmm2_final<<<(N_NODES + 7) / 8, 256>>>(b2, out);
}

// round 4
// speedup vs baseline: 1.9487x; 1.2863x over previous
#include <cuda_runtime.h>
#include <cuda_bf16.h>
#include <math.h>
#include <stdint.h>

#define N_NODES 50000
#define N_EDGES 800000
#define NFEAT 512
#define NHID 128
#define NCLASS 40

// ---- scratch (static device arrays; no allocation allowed) ----
__device__ float g_S[(size_t)N_NODES * 256];     // [xW1 | xWr1+br1]
__device__ float g_h[(size_t)N_NODES * 256];     // [relu(gc1) | xWr1+br1]
__device__ float g_T[(size_t)N_NODES * 80];      // [hW2 | hWr2+br2]
__device__ float g_Wc2[256 * 80];                // [W2 | Wr2]
__device__ float g_bc1[256];                     // [0 | br1]
__device__ float g_bc2[80];                      // [0 | br2]
// CSR-by-destination build
__device__ int   g_counts[N_NODES];
__device__ int   g_row_start[N_NODES + 1];
__device__ int   g_cursor[N_NODES];
__device__ int   g_es[N_EDGES];
__device__ float g_ev[N_EDGES];
// bf16 split operands for HMMA GEMM1
__device__ __align__(16) __nv_bfloat16 g_Ah[(size_t)N_NODES * NFEAT];
__device__ __align__(16) __nv_bfloat16 g_Al[(size_t)N_NODES * NFEAT];
__device__ __align__(16) __nv_bfloat16 g_Bth[256 * NFEAT];  // [n][k] transposed hi
__device__ __align__(16) __nv_bfloat16 g_Btl[256 * NFEAT];  // [n][k] transposed lo

// ================= helpers =================
__device__ __forceinline__ uint32_t smem_u32(const void* p) {
    uint32_t a;
    asm("{ .reg .u64 t; cvta.to.shared.u64 t, %1; cvt.u32.u64 %0, t; }" : "=r"(a) : "l"(p));
    return a;
}
#define CP_ASYNC16(dst, src) \
    asm volatile("cp.async.cg.shared.global [%0], [%1], 16;" :: "r"(dst), "l"(src) : "memory")
#define CP_COMMIT() asm volatile("cp.async.commit_group;" ::: "memory")
#define CP_WAIT(n)  asm volatile("cp.async.wait_group %0;" :: "n"(n) : "memory")

__device__ __forceinline__ void ldmx4(uint32_t addr, uint32_t& r0, uint32_t& r1,
                                      uint32_t& r2, uint32_t& r3) {
    asm volatile("ldmatrix.sync.aligned.m8n8.x4.shared.b16 {%0,%1,%2,%3}, [%4];"
                 : "=r"(r0), "=r"(r1), "=r"(r2), "=r"(r3) : "r"(addr));
}
__device__ __forceinline__ void mma16816(float& c0, float& c1, float& c2, float& c3,
                                         uint32_t a0, uint32_t a1, uint32_t a2, uint32_t a3,
                                         uint32_t b0, uint32_t b1) {
    asm volatile("mma.sync.aligned.m16n8k16.row.col.f32.bf16.bf16.f32 "
                 "{%0,%1,%2,%3}, {%4,%5,%6,%7}, {%8,%9}, {%0,%1,%2,%3};"
                 : "+f"(c0), "+f"(c1), "+f"(c2), "+f"(c3)
                 : "r"(a0), "r"(a1), "r"(a2), "r"(a3), "r"(b0), "r"(b1));
}

// ---- pack: Bt hi/lo transposed, Wc2, biases, zero hist ----
__global__ void pack_kernel(const float* __restrict__ W1, const float* __restrict__ Wr1,
                            const float* __restrict__ br1,
                            const float* __restrict__ W2, const float* __restrict__ Wr2,
                            const float* __restrict__ br2) {
    int idx = blockIdx.x * blockDim.x + threadIdx.x;
    if (idx < NFEAT * 256) {
        int k = idx >> 8, n = idx & 255;
        float w = (n < 128) ? W1[k * 128 + n] : Wr1[k * 128 + (n - 128)];
        __nv_bfloat16 hi = __float2bfloat16(w);
        __nv_bfloat16 lo = __float2bfloat16(w - __bfloat162float(hi));
        g_Bth[(size_t)n * NFEAT + k] = hi;
        g_Btl[(size_t)n * NFEAT + k] = lo;
    }
    if (idx < 256 * 80) {
        int k = idx / 80, j = idx % 80;
        g_Wc2[idx] = (j < 40) ? W2[k * 40 + j] : Wr2[k * 40 + (j - 40)];
    }
    if (idx < 256) g_bc1[idx] = (idx < 128) ? 0.f : br1[idx - 128];
    if (idx < 80)  g_bc2[idx] = (idx < 40) ? 0.f : br2[idx - 40];
    if (idx < N_NODES) g_counts[idx] = 0;
}

// ---- convert x -> Ah, Al (bf16 hi/lo), row-major ----
__global__ void convertA_kernel(const float* __restrict__ x) {
    int gid = blockIdx.x * blockDim.x + threadIdx.x;  // 8 fp32 per thread
    if (gid >= N_NODES * (NFEAT / 8)) return;
    const float4* p = (const float4*)&x[(size_t)gid * 8];
    float4 v0 = p[0], v1 = p[1];
    float f[8] = {v0.x, v0.y, v0.z, v0.w, v1.x, v1.y, v1.z, v1.w};
    uint32_t hw[4], lw[4];
#pragma unroll
    for (int q = 0; q < 4; q++) {
        __nv_bfloat16 h0 = __float2bfloat16(f[2 * q]);
        __nv_bfloat16 h1 = __float2bfloat16(f[2 * q + 1]);
        __nv_bfloat16 l0 = __float2bfloat16(f[2 * q] - __bfloat162float(h0));
        __nv_bfloat16 l1 = __float2bfloat16(f[2 * q + 1] - __bfloat162float(h1));
        union { __nv_bfloat162 b; uint32_t u; } ch, cl;
        ch.b.x = h0; ch.b.y = h1; cl.b.x = l0; cl.b.y = l1;
        hw[q] = ch.u; lw[q] = cl.u;
    }
    *(uint4*)&g_Ah[(size_t)gid * 8] = make_uint4(hw[0], hw[1], hw[2], hw[3]);
    *(uint4*)&g_Al[(size_t)gid * 8] = make_uint4(lw[0], lw[1], lw[2], lw[3]);
}

// ---- GEMM1 via mma.sync bf16 3-term: g_S = x @ [W1|Wr1] + [0|br1] ----
// CTA tile 128x128x32, 8 warps (4M x 2N), warp tile 32x64.
#define ARR_SZ (128 * 40 * 2)        // bytes per smem array (80B padded rows)
#define STG_SZ (4 * ARR_SZ)          // 40960
#define GEMM1_SMEM (2 * STG_SZ)      // 81920

__global__ __launch_bounds__(256, 1) void gemm1_mma() {
    extern __shared__ unsigned char smem[];
    uint32_t sb = smem_u32(smem);
    int tid = threadIdx.x, lane = tid & 31, wid = tid >> 5;
    int warp_m = wid & 3, warp_n = wid >> 2;
    int brow = blockIdx.x * 128;
    int bcol = blockIdx.y * 128;
    int grp = lane >> 3, rr = lane & 7;

    float acc[2][8][4];
#pragma unroll
    for (int i = 0; i < 2; i++)
#pragma unroll
        for (int j = 0; j < 8; j++)
#pragma unroll
            for (int q = 0; q < 4; q++) acc[i][j][q] = 0.f;

    const __nv_bfloat16* gsrc[4] = {g_Ah, g_Al, g_Bth, g_Btl};

#define LOAD_STAGE(stage, k0) do { \
    _Pragma("unroll") \
    for (int arr = 0; arr < 4; arr++) { \
        _Pragma("unroll") \
        for (int rep = 0; rep < 2; rep++) { \
            int q = tid + rep * 256; \
            int row = q >> 2, c16 = q & 3; \
            uint32_t dst = sb + (stage) * STG_SZ + arr * ARR_SZ + row * 80 + c16 * 16; \
            const __nv_bfloat16* src; \
            if (arr < 2) { \
                int rg = brow + row; if (rg >= N_NODES) rg = N_NODES - 1; \
                src = gsrc[arr] + (size_t)rg * NFEAT + (k0) + c16 * 8; \
            } else { \
                src = gsrc[arr] + (size_t)(bcol + row) * NFEAT + (k0) + c16 * 8; \
            } \
            CP_ASYNC16(dst, src); \
        } \
    } \
    CP_COMMIT(); \
} while (0)

    LOAD_STAGE(0, 0);

    int cur = 0;
    for (int s = 0; s < 16; s++) {
        if (s < 15) {
            LOAD_STAGE(1 - cur, (s + 1) * 32);
            CP_WAIT(1);
        } else {
            CP_WAIT(0);
        }
        __syncthreads();

        uint32_t base = sb + cur * STG_SZ;
#pragma unroll
        for (int k16 = 0; k16 < 32; k16 += 16) {
            uint32_t ah[2][4], al[2][4], bh[4][4], bl[4][4];
#pragma unroll
            for (int mi = 0; mi < 2; mi++) {
                uint32_t ao = base + (uint32_t)((warp_m * 32 + mi * 16 + (grp & 1) * 8 + rr) * 80
                                                + (k16 + (grp >> 1) * 8) * 2);
                ldmx4(ao + 0 * ARR_SZ, ah[mi][0], ah[mi][1], ah[mi][2], ah[mi][3]);
                ldmx4(ao + 1 * ARR_SZ, al[mi][0], al[mi][1], al[mi][2], al[mi][3]);
            }
#pragma unroll
            for (int p = 0; p < 4; p++) {
                uint32_t bo = base + (uint32_t)((warp_n * 64 + p * 16 + (grp >> 1) * 8 + rr) * 80
                                                + (k16 + (grp & 1) * 8) * 2);
                ldmx4(bo + 2 * ARR_SZ, bh[p][0], bh[p][1], bh[p][2], bh[p][3]);
                ldmx4(bo + 3 * ARR_SZ, bl[p][0], bl[p][1], bl[p][2], bl[p][3]);
            }
#pragma unroll
            for (int mi = 0; mi < 2; mi++) {
#pragma unroll
                for (int ni = 0; ni < 8; ni++) {
                    uint32_t b0h = bh[ni >> 1][(ni & 1) * 2], b1h = bh[ni >> 1][(ni & 1) * 2 + 1];
                    uint32_t b0l = bl[ni >> 1][(ni & 1) * 2], b1l = bl[ni >> 1][(ni & 1) * 2 + 1];
                    float* c = acc[mi][ni];
                    mma16816(c[0], c[1], c[2], c[3],
                             ah[mi][0], ah[mi][1], ah[mi][2], ah[mi][3], b0h, b1h);
                    mma16816(c[0], c[1], c[2], c[3],
                             ah[mi][0], ah[mi][1], ah[mi][2], ah[mi][3], b0l, b1l);
                    mma16816(c[0], c[1], c[2], c[3],
                             al[mi][0], al[mi][1], al[mi][2], al[mi][3], b0h, b1h);
                }
            }
        }
        __syncthreads();
        cur ^= 1;
    }

#pragma unroll
    for (int mi = 0; mi < 2; mi++) {
        int r0 = brow + warp_m * 32 + mi * 16 + (lane >> 2);
#pragma unroll
        for (int ni = 0; ni < 8; ni++) {
            int c = bcol + warp_n * 64 + ni * 8 + (lane & 3) * 2;
            float bx = g_bc1[c], by = g_bc1[c + 1];
            float* cc = acc[mi][ni];
            if (r0 < N_NODES)
                *(float2*)&g_S[(size_t)r0 * 256 + c] = make_float2(cc[0] + bx, cc[1] + by);
            if (r0 + 8 < N_NODES)
                *(float2*)&g_S[(size_t)(r0 + 8) * 256 + c] = make_float2(cc[2] + bx, cc[3] + by);
        }
    }
}

// ---- histogram / scan / scatter (CSR build) ----
__global__ void hist_kernel(const int* __restrict__ dst) {
    int e = blockIdx.x * blockDim.x + threadIdx.x;
    if (e < N_EDGES) atomicAdd(&g_counts[dst[e]], 1);
}

__global__ void scan_kernel() {
    __shared__ int buf[2][1024];
    int tid = threadIdx.x;
    int offset = 0;
    for (int base = 0; base < N_NODES; base += 1024) {
        int i = base + tid;
        int c = (i < N_NODES) ? g_counts[i] : 0;
        int cur = 0;
        buf[0][tid] = c;
        __syncthreads();
#pragma unroll
        for (int d = 1; d < 1024; d <<= 1) {
            int v = buf[cur][tid];
            if (tid >= d) v += buf[cur][tid - d];
            buf[1 - cur][tid] = v;
            cur ^= 1;
            __syncthreads();
        }
        int incl = buf[cur][tid];
        int tot = buf[cur][1023];
        if (i < N_NODES) {
            int ex = offset + incl - c;
            g_row_start[i] = ex;
            g_cursor[i] = ex;
        }
        offset += tot;
        __syncthreads();
    }
    if (tid == 0) g_row_start[N_NODES] = offset;
}

__global__ void scatter_kernel(const int* __restrict__ src, const int* __restrict__ dst,
                               const float* __restrict__ val) {
    int e = blockIdx.x * blockDim.x + threadIdx.x;
    if (e >= N_EDGES) return;
    int d = dst[e];
    int p = atomicAdd(&g_cursor[d], 1);
    g_es[p] = src[e];
    g_ev[p] = val[e];
}

// ---- SpMM1 (CSR, warp per dst row) fused: bias + relu + residual copy -> h ----
__global__ void spmm1_csr(const float* __restrict__ b1) {
    int w = (blockIdx.x * blockDim.x + threadIdx.x) >> 5;
    int lane = threadIdx.x & 31;
    if (w >= N_NODES) return;
    int e = g_row_start[w];
    int end = g_row_start[w + 1];
    float4 acc = *(const float4*)&b1[lane * 4];
    for (; e + 2 <= end; e += 2) {
        int s0 = g_es[e], s1 = g_es[e + 1];
        float v0 = g_ev[e], v1 = g_ev[e + 1];
        float4 x0 = *(const float4*)&g_S[(size_t)s0 * 256 + lane * 4];
        float4 x1 = *(const float4*)&g_S[(size_t)s1 * 256 + lane * 4];
        acc.x = fmaf(v0, x0.x, acc.x); acc.y = fmaf(v0, x0.y, acc.y);
        acc.z = fmaf(v0, x0.z, acc.z); acc.w = fmaf(v0, x0.w, acc.w);
        acc.x = fmaf(v1, x1.x, acc.x); acc.y = fmaf(v1, x1.y, acc.y);
        acc.z = fmaf(v1, x1.z, acc.z); acc.w = fmaf(v1, x1.w, acc.w);
    }
    if (e < end) {
        int s0 = g_es[e];
        float v0 = g_ev[e];
        float4 x0 = *(const float4*)&g_S[(size_t)s0 * 256 + lane * 4];
        acc.x = fmaf(v0, x0.x, acc.x); acc.y = fmaf(v0, x0.y, acc.y);
        acc.z = fmaf(v0, x0.z, acc.z); acc.w = fmaf(v0, x0.w, acc.w);
    }
    float4 o;
    o.x = fmaxf(acc.x, 0.f); o.y = fmaxf(acc.y, 0.f);
    o.z = fmaxf(acc.z, 0.f); o.w = fmaxf(acc.w, 0.f);
    *(float4*)&g_h[(size_t)w * 256 + lane * 4] = o;
    float4 r = *(const float4*)&g_S[(size_t)w * 256 + 128 + lane * 4];
    *(float4*)&g_h[(size_t)w * 256 + 128 + lane * 4] = r;
}

// ---- SGEMM 128x80x16 fp32: T = h @ [W2|Wr2] + [0|br2] ----
__global__ __launch_bounds__(256) void sgemm_n80(const float* __restrict__ A,
                                                 const float* __restrict__ B,
                                                 const float* __restrict__ bias,
                                                 float* __restrict__ C,
                                                 int M, int K) {
    __shared__ float As[16][132];
    __shared__ float Bs[16][80];
    int tid = threadIdx.x;
    int brow = blockIdx.x * 128;
    int ar0 = tid >> 2;
    int ak = (tid & 3) * 4;
    int tx = tid & 15, ty = tid >> 4;

    float acc[8][5] = {};

    for (int k0 = 0; k0 < K; k0 += 16) {
#pragma unroll
        for (int h = 0; h < 2; h++) {
            int r = brow + ar0 + h * 64;
            float4 v = make_float4(0.f, 0.f, 0.f, 0.f);
            if (r < M) v = *(const float4*)&A[(size_t)r * K + k0 + ak];
            As[ak + 0][ar0 + h * 64] = v.x;
            As[ak + 1][ar0 + h * 64] = v.y;
            As[ak + 2][ar0 + h * 64] = v.z;
            As[ak + 3][ar0 + h * 64] = v.w;
        }
#pragma unroll
        for (int h = 0; h < 5; h++) {
            int idx = h * 256 + tid;
            int kr = idx / 80, c = idx - kr * 80;
            Bs[kr][c] = B[(size_t)(k0 + kr) * 80 + c];
        }
        __syncthreads();
#pragma unroll
        for (int k = 0; k < 16; k++) {
            float a[8], b[5];
            *(float4*)&a[0] = *(const float4*)&As[k][ty * 8];
            *(float4*)&a[4] = *(const float4*)&As[k][ty * 8 + 4];
#pragma unroll
            for (int j = 0; j < 5; j++) b[j] = Bs[k][tx * 5 + j];
#pragma unroll
            for (int i = 0; i < 8; i++)
#pragma unroll
                for (int j = 0; j < 5; j++)
                    acc[i][j] = fmaf(a[i], b[j], acc[i][j]);
        }
        __syncthreads();
    }

#pragma unroll
    for (int i = 0; i < 8; i++) {
        int r = brow + ty * 8 + i;
        if (r >= M) continue;
#pragma unroll
        for (int j = 0; j < 5; j++) {
            int c = tx * 5 + j;
            C[(size_t)r * 80 + c] = acc[i][j] + bias[c];
        }
    }
}

// ---- SpMM2 (CSR, warp per dst row) fused: bias + residual + log_softmax -> out ----
__global__ void spmm2_final(const float* __restrict__ b2, float* __restrict__ out) {
    int w = (blockIdx.x * blockDim.x + threadIdx.x) >> 5;
    int lane = threadIdx.x & 31;
    if (w >= N_NODES) return;
    int e = g_row_start[w];
    int end = g_row_start[w + 1];
    bool act = lane < 20;
    float ax = 0.f, ay = 0.f;
    if (act) { ax = b2[2 * lane]; ay = b2[2 * lane + 1]; }
    for (; e + 2 <= end; e += 2) {
        int s0 = g_es[e], s1 = g_es[e + 1];
        float v0 = g_ev[e], v1 = g_ev[e + 1];
        if (act) {
            float2 t0 = *(const float2*)&g_T[(size_t)s0 * 80 + 2 * lane];
            float2 t1 = *(const float2*)&g_T[(size_t)s1 * 80 + 2 * lane];
            ax = fmaf(v0, t0.x, ax); ay = fmaf(v0, t0.y, ay);
            ax = fmaf(v1, t1.x, ax); ay = fmaf(v1, t1.y, ay);
        }
    }
    if (e < end) {
        int s0 = g_es[e];
        float v0 = g_ev[e];
        if (act) {
            float2 t0 = *(const float2*)&g_T[(size_t)s0 * 80 + 2 * lane];
            ax = fmaf(v0, t0.x, ax); ay = fmaf(v0, t0.y, ay);
        }
    }
    if (act) {
        float2 r = *(const float2*)&g_T[(size_t)w * 80 + 40 + 2 * lane];
        ax += r.x; ay += r.y;
    }
    float m = act ? fmaxf(ax, ay) : -INFINITY;
#pragma unroll
    for (int o = 16; o > 0; o >>= 1) m = fmaxf(m, __shfl_xor_sync(0xffffffffu, m, o));
    float s = act ? (__expf(ax - m) + __expf(ay - m)) : 0.f;
#pragma unroll
    for (int o = 16; o > 0; o >>= 1) s += __shfl_xor_sync(0xffffffffu, s, o);
    float lse = m + logf(s);
    if (act) {
        out[(size_t)w * 40 + 2 * lane + 0] = ax - lse;
        out[(size_t)w * 40 + 2 * lane + 1] = ay - lse;
    }
}

extern "C" void kernel_launch(void* const* d_in, const int* in_sizes, int n_in,
                              void* d_out, int out_size) {
    const float* x    = (const float*)d_in[0];
    const int*   esrc = (const int*)d_in[1];
    const int*   edst = (const int*)d_in[2];
    const float* eval_= (const float*)d_in[3];
    const float* W1   = (const float*)d_in[4];
    const float* b1   = (const float*)d_in[5];
    const float* Wr1  = (const float*)d_in[6];
    const float* br1  = (const float*)d_in[7];
    const float* W2   = (const float*)d_in[8];
    const float* b2   = (const float*)d_in[9];
    const float* Wr2  = (const float*)d_in[10];
    const float* br2  = (const float*)d_in[11];
    float* out = (float*)d_out;

    void *pH, *pT, *pWc2, *pBc2;
    cudaGetSymbolAddress(&pH, g_h);
    cudaGetSymbolAddress(&pT, g_T);
    cudaGetSymbolAddress(&pWc2, g_Wc2);
    cudaGetSymbolAddress(&pBc2, g_bc2);

    static bool attr_set = false;
    if (!attr_set) {
        cudaFuncSetAttribute(gemm1_mma, cudaFuncAttributeMaxDynamicSharedMemorySize, GEMM1_SMEM);
        attr_set = true;
    }

    // 1. pack (Bt hi/lo, Wc2, biases, zero hist)
    pack_kernel<<<512, 256>>>(W1, Wr1, br1, W2, Wr2, br2);
    // 2. convert x -> bf16 hi/lo
    convertA_kernel<<<(N_NODES * (NFEAT / 8) + 255) / 256, 256>>>(x);
    // 3. histogram (independent of GEMM)
    hist_kernel<<<(N_EDGES + 255) / 256, 256>>>(edst);
    // 4. GEMM1: S = x @ [W1|Wr1] + [0|br1]  (HMMA bf16 3-term)
    {
        dim3 grid((N_NODES + 127) / 128, 2);
        gemm1_mma<<<grid, 256, GEMM1_SMEM>>>();
    }
    // 5-6. CSR scan + scatter
    scan_kernel<<<1, 1024>>>();
    scatter_kernel<<<(N_EDGES + 255) / 256, 256>>>(esrc, edst, eval_);
    // 7. h = [relu(b1 + spmm(S[:,:128])) | S[:,128:]]
    spmm1_csr<<<(N_NODES + 7) / 8, 256>>>(b1);
    // 8. T = h @ [W2|Wr2] (+[0|br2])
    sgemm_n80<<<(N_NODES + 127) / 128, 256>>>((const float*)pH, (const float*)pWc2,
                                              (const float*)pBc2, (float*)pT,
                                              N_NODES, 256);
    // 9. out = log_softmax(b2 + spmm(T[:,:40]) + T[:,40:])
    spmm2_final<<<(N_NODES + 7) / 8, 256>>>(b2, out);
}

// round 6
// speedup vs baseline: 2.2870x; 1.1736x over previous
#include <cuda_runtime.h>
#include <cuda_bf16.h>
#include <math.h>
#include <stdint.h>

#define N_NODES 50000
#define N_EDGES 800000
#define NFEAT 512
#define NHID 128
#define NCLASS 40

// ---- scratch (static device arrays; no allocation allowed) ----
__device__ float g_S[(size_t)N_NODES * 256];     // [xW1 | xWr1+br1]
__device__ float g_h[(size_t)N_NODES * 256];     // [relu(gc1) | xWr1+br1]
__device__ float g_T[(size_t)N_NODES * 80];      // [hW2 | hWr2+br2]
__device__ float g_Wc2[256 * 80];                // [W2 | Wr2]
__device__ float g_bc1[256];                     // [0 | br1]
__device__ float g_bc2[80];                      // [0 | br2]
// CSR-by-destination build
__device__ int   g_counts[N_NODES];
__device__ int   g_row_start[N_NODES + 1];
__device__ int   g_cursor[N_NODES];
__device__ int   g_es[N_EDGES];
__device__ float g_ev[N_EDGES];
// bf16 split operands for HMMA GEMM1
__device__ __align__(16) __nv_bfloat16 g_Ah[(size_t)N_NODES * NFEAT];
__device__ __align__(16) __nv_bfloat16 g_Al[(size_t)N_NODES * NFEAT];
__device__ __align__(16) __nv_bfloat16 g_Bth[256 * NFEAT];  // [n][k] transposed hi
__device__ __align__(16) __nv_bfloat16 g_Btl[256 * NFEAT];  // [n][k] transposed lo

// ================= helpers =================
__device__ __forceinline__ uint32_t smem_u32(const void* p) {
    uint32_t a;
    asm("{ .reg .u64 t; cvta.to.shared.u64 t, %1; cvt.u32.u64 %0, t; }" : "=r"(a) : "l"(p));
    return a;
}
#define CP_ASYNC16(dst, src) \
    asm volatile("cp.async.cg.shared.global [%0], [%1], 16;" :: "r"(dst), "l"(src) : "memory")
#define CP_COMMIT() asm volatile("cp.async.commit_group;" ::: "memory")
#define CP_WAIT(n)  asm volatile("cp.async.wait_group %0;" :: "n"(n) : "memory")

__device__ __forceinline__ void ldmx4(uint32_t addr, uint32_t& r0, uint32_t& r1,
                                      uint32_t& r2, uint32_t& r3) {
    asm volatile("ldmatrix.sync.aligned.m8n8.x4.shared.b16 {%0,%1,%2,%3}, [%4];"
                 : "=r"(r0), "=r"(r1), "=r"(r2), "=r"(r3) : "r"(addr));
}
__device__ __forceinline__ void mma16816(float& c0, float& c1, float& c2, float& c3,
                                         uint32_t a0, uint32_t a1, uint32_t a2, uint32_t a3,
                                         uint32_t b0, uint32_t b1) {
    asm volatile("mma.sync.aligned.m16n8k16.row.col.f32.bf16.bf16.f32 "
                 "{%0,%1,%2,%3}, {%4,%5,%6,%7}, {%8,%9}, {%0,%1,%2,%3};"
                 : "+f"(c0), "+f"(c1), "+f"(c2), "+f"(c3)
                 : "r"(a0), "r"(a1), "r"(a2), "r"(a3), "r"(b0), "r"(b1));
}

// ---- pack: Bt hi/lo transposed, Wc2, biases, zero hist ----
__global__ void pack_kernel(const float* __restrict__ W1, const float* __restrict__ Wr1,
                            const float* __restrict__ br1,
                            const float* __restrict__ W2, const float* __restrict__ Wr2,
                            const float* __restrict__ br2) {
    int idx = blockIdx.x * blockDim.x + threadIdx.x;
    if (idx < NFEAT * 256) {
        int k = idx >> 8, n = idx & 255;
        float w = (n < 128) ? W1[k * 128 + n] : Wr1[k * 128 + (n - 128)];
        __nv_bfloat16 hi = __float2bfloat16(w);
        __nv_bfloat16 lo = __float2bfloat16(w - __bfloat162float(hi));
        g_Bth[(size_t)n * NFEAT + k] = hi;
        g_Btl[(size_t)n * NFEAT + k] = lo;
    }
    if (idx < 256 * 80) {
        int k = idx / 80, j = idx % 80;
        g_Wc2[idx] = (j < 40) ? W2[k * 40 + j] : Wr2[k * 40 + (j - 40)];
    }
    if (idx < 256) g_bc1[idx] = (idx < 128) ? 0.f : br1[idx - 128];
    if (idx < 80)  g_bc2[idx] = (idx < 40) ? 0.f : br2[idx - 40];
    if (idx < N_NODES) g_counts[idx] = 0;
}

// ---- convert x -> Ah, Al (bf16 hi/lo), row-major ----
__global__ void convertA_kernel(const float* __restrict__ x) {
    int gid = blockIdx.x * blockDim.x + threadIdx.x;  // 8 fp32 per thread
    if (gid >= N_NODES * (NFEAT / 8)) return;
    const float4* p = (const float4*)&x[(size_t)gid * 8];
    float4 v0 = p[0], v1 = p[1];
    float f[8] = {v0.x, v0.y, v0.z, v0.w, v1.x, v1.y, v1.z, v1.w};
    uint32_t hw[4], lw[4];
#pragma unroll
    for (int q = 0; q < 4; q++) {
        __nv_bfloat16 h0 = __float2bfloat16(f[2 * q]);
        __nv_bfloat16 h1 = __float2bfloat16(f[2 * q + 1]);
        __nv_bfloat16 l0 = __float2bfloat16(f[2 * q] - __bfloat162float(h0));
        __nv_bfloat16 l1 = __float2bfloat16(f[2 * q + 1] - __bfloat162float(h1));
        union { __nv_bfloat162 b; uint32_t u; } ch, cl;
        ch.b.x = h0; ch.b.y = h1; cl.b.x = l0; cl.b.y = l1;
        hw[q] = ch.u; lw[q] = cl.u;
    }
    *(uint4*)&g_Ah[(size_t)gid * 8] = make_uint4(hw[0], hw[1], hw[2], hw[3]);
    *(uint4*)&g_Al[(size_t)gid * 8] = make_uint4(lw[0], lw[1], lw[2], lw[3]);
}

// ---- GEMM1 via mma.sync bf16 3-term: g_S = x @ [W1|Wr1] + [0|br1] ----
// CTA tile 128x128x32, 8 warps (4M x 2N), warp tile 32x64. 2 CTAs/SM.
#define ARR_SZ (128 * 40 * 2)        // bytes per smem array (80B padded rows)
#define STG_SZ (4 * ARR_SZ)          // 40960
#define GEMM1_SMEM (2 * STG_SZ)      // 81920

__global__ __launch_bounds__(256, 2) void gemm1_mma() {
    extern __shared__ unsigned char smem[];
    uint32_t sb = smem_u32(smem);
    int tid = threadIdx.x, lane = tid & 31, wid = tid >> 5;
    int warp_m = wid & 3, warp_n = wid >> 2;
    int brow = blockIdx.x * 128;
    int bcol = blockIdx.y * 128;
    int grp = lane >> 3, rr = lane & 7;

    float acc[2][8][4];
#pragma unroll
    for (int i = 0; i < 2; i++)
#pragma unroll
        for (int j = 0; j < 8; j++)
#pragma unroll
            for (int q = 0; q < 4; q++) acc[i][j][q] = 0.f;

    const __nv_bfloat16* gsrc[4] = {g_Ah, g_Al, g_Bth, g_Btl};

#define LOAD_STAGE(stage, k0) do { \
    _Pragma("unroll") \
    for (int arr = 0; arr < 4; arr++) { \
        _Pragma("unroll") \
        for (int rep = 0; rep < 2; rep++) { \
            int q = tid + rep * 256; \
            int row = q >> 2, c16 = q & 3; \
            uint32_t dst = sb + (stage) * STG_SZ + arr * ARR_SZ + row * 80 + c16 * 16; \
            const __nv_bfloat16* src; \
            if (arr < 2) { \
                int rg = brow + row; if (rg >= N_NODES) rg = N_NODES - 1; \
                src = gsrc[arr] + (size_t)rg * NFEAT + (k0) + c16 * 8; \
            } else { \
                src = gsrc[arr] + (size_t)(bcol + row) * NFEAT + (k0) + c16 * 8; \
            } \
            CP_ASYNC16(dst, src); \
        } \
    } \
    CP_COMMIT(); \
} while (0)

    LOAD_STAGE(0, 0);

    int cur = 0;
    for (int s = 0; s < 16; s++) {
        if (s < 15) {
            LOAD_STAGE(1 - cur, (s + 1) * 32);
            CP_WAIT(1);
        } else {
            CP_WAIT(0);
        }
        __syncthreads();

        uint32_t base = sb + cur * STG_SZ;
#pragma unroll
        for (int k16 = 0; k16 < 32; k16 += 16) {
            uint32_t ah[2][4], al[2][4], bh[4][4], bl[4][4];
#pragma unroll
            for (int mi = 0; mi < 2; mi++) {
                uint32_t ao = base + (uint32_t)((warp_m * 32 + mi * 16 + (grp & 1) * 8 + rr) * 80
                                                + (k16 + (grp >> 1) * 8) * 2);
                ldmx4(ao + 0 * ARR_SZ, ah[mi][0], ah[mi][1], ah[mi][2], ah[mi][3]);
                ldmx4(ao + 1 * ARR_SZ, al[mi][0], al[mi][1], al[mi][2], al[mi][3]);
            }
#pragma unroll
            for (int p = 0; p < 4; p++) {
                uint32_t bo = base + (uint32_t)((warp_n * 64 + p * 16 + (grp >> 1) * 8 + rr) * 80
                                                + (k16 + (grp & 1) * 8) * 2);
                ldmx4(bo + 2 * ARR_SZ, bh[p][0], bh[p][1], bh[p][2], bh[p][3]);
                ldmx4(bo + 3 * ARR_SZ, bl[p][0], bl[p][1], bl[p][2], bl[p][3]);
            }
#pragma unroll
            for (int mi = 0; mi < 2; mi++) {
#pragma unroll
                for (int ni = 0; ni < 8; ni++) {
                    uint32_t b0h = bh[ni >> 1][(ni & 1) * 2], b1h = bh[ni >> 1][(ni & 1) * 2 + 1];
                    uint32_t b0l = bl[ni >> 1][(ni & 1) * 2], b1l = bl[ni >> 1][(ni & 1) * 2 + 1];
                    float* c = acc[mi][ni];
                    mma16816(c[0], c[1], c[2], c[3],
                             ah[mi][0], ah[mi][1], ah[mi][2], ah[mi][3], b0h, b1h);
                    mma16816(c[0], c[1], c[2], c[3],
                             ah[mi][0], ah[mi][1], ah[mi][2], ah[mi][3], b0l, b1l);
                    mma16816(c[0], c[1], c[2], c[3],
                             al[mi][0], al[mi][1], al[mi][2], al[mi][3], b0h, b1h);
                }
            }
        }
        __syncthreads();
        cur ^= 1;
    }

#pragma unroll
    for (int mi = 0; mi < 2; mi++) {
        int r0 = brow + warp_m * 32 + mi * 16 + (lane >> 2);
#pragma unroll
        for (int ni = 0; ni < 8; ni++) {
            int c = bcol + warp_n * 64 + ni * 8 + (lane & 3) * 2;
            float bx = g_bc1[c], by = g_bc1[c + 1];
            float* cc = acc[mi][ni];
            if (r0 < N_NODES)
                *(float2*)&g_S[(size_t)r0 * 256 + c] = make_float2(cc[0] + bx, cc[1] + by);
            if (r0 + 8 < N_NODES)
                *(float2*)&g_S[(size_t)(r0 + 8) * 256 + c] = make_float2(cc[2] + bx, cc[3] + by);
        }
    }
}

// ---- histogram / scan / scatter (CSR build) ----
__global__ void hist_kernel(const int* __restrict__ dst) {
    int e = blockIdx.x * blockDim.x + threadIdx.x;
    if (e < N_EDGES) atomicAdd(&g_counts[dst[e]], 1);
}

// single-block shuffle-based scan: 1024 threads, 49 chunks, 3 syncs each
__global__ void scan_kernel() {
    __shared__ int wsum[32];
    __shared__ int chunk_total;
    int tid = threadIdx.x, lane = tid & 31, w = tid >> 5;
    int offset = 0;
    for (int base = 0; base < N_NODES; base += 1024) {
        int i = base + tid;
        int c = (i < N_NODES) ? g_counts[i] : 0;
        int v = c;
#pragma unroll
        for (int d = 1; d < 32; d <<= 1) {
            int t = __shfl_up_sync(0xffffffffu, v, d);
            if (lane >= d) v += t;
        }
        if (lane == 31) wsum[w] = v;
        __syncthreads();
        if (w == 0) {
            int s = wsum[lane];
#pragma unroll
            for (int d = 1; d < 32; d <<= 1) {
                int t = __shfl_up_sync(0xffffffffu, s, d);
                if (lane >= d) s += t;
            }
            wsum[lane] = s;
            if (lane == 31) chunk_total = s;
        }
        __syncthreads();
        int warp_prefix = (w == 0) ? 0 : wsum[w - 1];
        int excl = v - c + warp_prefix + offset;
        if (i < N_NODES) {
            g_row_start[i] = excl;
            g_cursor[i] = excl;
        }
        offset += chunk_total;
        __syncthreads();
    }
    if (tid == 0) g_row_start[N_NODES] = offset;
}

__global__ void scatter_kernel(const int* __restrict__ src, const int* __restrict__ dst,
                               const float* __restrict__ val) {
    int e = blockIdx.x * blockDim.x + threadIdx.x;
    if (e >= N_EDGES) return;
    int d = dst[e];
    int p = atomicAdd(&g_cursor[d], 1);
    g_es[p] = src[e];
    g_ev[p] = val[e];
}

// ---- SpMM1 (CSR, warp per dst row, 4-edge unroll) fused epilogue -> h ----
__global__ void spmm1_csr(const float* __restrict__ b1) {
    int w = (blockIdx.x * blockDim.x + threadIdx.x) >> 5;
    int lane = threadIdx.x & 31;
    if (w >= N_NODES) return;
    int e = g_row_start[w];
    int end = g_row_start[w + 1];
    float4 acc = *(const float4*)&b1[lane * 4];
    for (; e + 4 <= end; e += 4) {
        int s0 = g_es[e], s1 = g_es[e + 1], s2 = g_es[e + 2], s3 = g_es[e + 3];
        float v0 = g_ev[e], v1 = g_ev[e + 1], v2 = g_ev[e + 2], v3 = g_ev[e + 3];
        float4 x0 = *(const float4*)&g_S[(size_t)s0 * 256 + lane * 4];
        float4 x1 = *(const float4*)&g_S[(size_t)s1 * 256 + lane * 4];
        float4 x2 = *(const float4*)&g_S[(size_t)s2 * 256 + lane * 4];
        float4 x3 = *(const float4*)&g_S[(size_t)s3 * 256 + lane * 4];
        acc.x = fmaf(v0, x0.x, acc.x); acc.y = fmaf(v0, x0.y, acc.y);
        acc.z = fmaf(v0, x0.z, acc.z); acc.w = fmaf(v0, x0.w, acc.w);
        acc.x = fmaf(v1, x1.x, acc.x); acc.y = fmaf(v1, x1.y, acc.y);
        acc.z = fmaf(v1, x1.z, acc.z); acc.w = fmaf(v1, x1.w, acc.w);
        acc.x = fmaf(v2, x2.x, acc.x); acc.y = fmaf(v2, x2.y, acc.y);
        acc.z = fmaf(v2, x2.z, acc.z); acc.w = fmaf(v2, x2.w, acc.w);
        acc.x = fmaf(v3, x3.x, acc.x); acc.y = fmaf(v3, x3.y, acc.y);
        acc.z = fmaf(v3, x3.z, acc.z); acc.w = fmaf(v3, x3.w, acc.w);
    }
    for (; e < end; e++) {
        int s0 = g_es[e];
        float v0 = g_ev[e];
        float4 x0 = *(const float4*)&g_S[(size_t)s0 * 256 + lane * 4];
        acc.x = fmaf(v0, x0.x, acc.x); acc.y = fmaf(v0, x0.y, acc.y);
        acc.z = fmaf(v0, x0.z, acc.z); acc.w = fmaf(v0, x0.w, acc.w);
    }
    float4 o;
    o.x = fmaxf(acc.x, 0.f); o.y = fmaxf(acc.y, 0.f);
    o.z = fmaxf(acc.z, 0.f); o.w = fmaxf(acc.w, 0.f);
    *(float4*)&g_h[(size_t)w * 256 + lane * 4] = o;
    float4 r = *(const float4*)&g_S[(size_t)w * 256 + 128 + lane * 4];
    *(float4*)&g_h[(size_t)w * 256 + 128 + lane * 4] = r;
}

// ---- SGEMM 128x80x16 fp32: T = h @ [W2|Wr2] + [0|br2] ----
__global__ __launch_bounds__(256) void sgemm_n80(const float* __restrict__ A,
                                                 const float* __restrict__ B,
                                                 const float* __restrict__ bias,
                                                 float* __restrict__ C,
                                                 int M, int K) {
    __shared__ float As[16][132];
    __shared__ float Bs[16][80];
    int tid = threadIdx.x;
    int brow = blockIdx.x * 128;
    int ar0 = tid >> 2;
    int ak = (tid & 3) * 4;
    int tx = tid & 15, ty = tid >> 4;

    float acc[8][5] = {};

    for (int k0 = 0; k0 < K; k0 += 16) {
#pragma unroll
        for (int h = 0; h < 2; h++) {
            int r = brow + ar0 + h * 64;
            float4 v = make_float4(0.f, 0.f, 0.f, 0.f);
            if (r < M) v = *(const float4*)&A[(size_t)r * K + k0 + ak];
            As[ak + 0][ar0 + h * 64] = v.x;
            As[ak + 1][ar0 + h * 64] = v.y;
            As[ak + 2][ar0 + h * 64] = v.z;
            As[ak + 3][ar0 + h * 64] = v.w;
        }
#pragma unroll
        for (int h = 0; h < 5; h++) {
            int idx = h * 256 + tid;
            int kr = idx / 80, c = idx - kr * 80;
            Bs[kr][c] = B[(size_t)(k0 + kr) * 80 + c];
        }
        __syncthreads();
#pragma unroll
        for (int k = 0; k < 16; k++) {
            float a[8], b[5];
            *(float4*)&a[0] = *(const float4*)&As[k][ty * 8];
            *(float4*)&a[4] = *(const float4*)&As[k][ty * 8 + 4];
#pragma unroll
            for (int j = 0; j < 5; j++) b[j] = Bs[k][tx * 5 + j];
#pragma unroll
            for (int i = 0; i < 8; i++)
#pragma unroll
                for (int j = 0; j < 5; j++)
                    acc[i][j] = fmaf(a[i], b[j], acc[i][j]);
        }
        __syncthreads();
    }

#pragma unroll
    for (int i = 0; i < 8; i++) {
        int r = brow + ty * 8 + i;
        if (r >= M) continue;
#pragma unroll
        for (int j = 0; j < 5; j++) {
            int c = tx * 5 + j;
            C[(size_t)r * 80 + c] = acc[i][j] + bias[c];
        }
    }
}

// ---- SpMM2 (CSR, warp per dst row, 4-edge unroll) fused final -> out ----
__global__ void spmm2_final(const float* __restrict__ b2, float* __restrict__ out) {
    int w = (blockIdx.x * blockDim.x + threadIdx.x) >> 5;
    int lane = threadIdx.x & 31;
    if (w >= N_NODES) return;
    int e = g_row_start[w];
    int end = g_row_start[w + 1];
    bool act = lane < 20;
    float ax = 0.f, ay = 0.f;
    if (act) { ax = b2[2 * lane]; ay = b2[2 * lane + 1]; }
    for (; e + 4 <= end; e += 4) {
        int s0 = g_es[e], s1 = g_es[e + 1], s2 = g_es[e + 2], s3 = g_es[e + 3];
        float v0 = g_ev[e], v1 = g_ev[e + 1], v2 = g_ev[e + 2], v3 = g_ev[e + 3];
        if (act) {
            float2 t0 = *(const float2*)&g_T[(size_t)s0 * 80 + 2 * lane];
            float2 t1 = *(const float2*)&g_T[(size_t)s1 * 80 + 2 * lane];
            float2 t2 = *(const float2*)&g_T[(size_t)s2 * 80 + 2 * lane];
            float2 t3 = *(const float2*)&g_T[(size_t)s3 * 80 + 2 * lane];
            ax = fmaf(v0, t0.x, ax); ay = fmaf(v0, t0.y, ay);
            ax = fmaf(v1, t1.x, ax); ay = fmaf(v1, t1.y, ay);
            ax = fmaf(v2, t2.x, ax); ay = fmaf(v2, t2.y, ay);
            ax = fmaf(v3, t3.x, ax); ay = fmaf(v3, t3.y, ay);
        }
    }
    for (; e < end; e++) {
        int s0 = g_es[e];
        float v0 = g_ev[e];
        if (act) {
            float2 t0 = *(const float2*)&g_T[(size_t)s0 * 80 + 2 * lane];
            ax = fmaf(v0, t0.x, ax); ay = fmaf(v0, t0.y, ay);
        }
    }
    if (act) {
        float2 r = *(const float2*)&g_T[(size_t)w * 80 + 40 + 2 * lane];
        ax += r.x; ay += r.y;
    }
    float m = act ? fmaxf(ax, ay) : -INFINITY;
#pragma unroll
    for (int o = 16; o > 0; o >>= 1) m = fmaxf(m, __shfl_xor_sync(0xffffffffu, m, o));
    float s = act ? (__expf(ax - m) + __expf(ay - m)) : 0.f;
#pragma unroll
    for (int o = 16; o > 0; o >>= 1) s += __shfl_xor_sync(0xffffffffu, s, o);
    float lse = m + logf(s);
    if (act) {
        out[(size_t)w * 40 + 2 * lane + 0] = ax - lse;
        out[(size_t)w * 40 + 2 * lane + 1] = ay - lse;
    }
}

extern "C" void kernel_launch(void* const* d_in, const int* in_sizes, int n_in,
                              void* d_out, int out_size) {
    const float* x    = (const float*)d_in[0];
    const int*   esrc = (const int*)d_in[1];
    const int*   edst = (const int*)d_in[2];
    const float* eval_= (const float*)d_in[3];
    const float* W1   = (const float*)d_in[4];
    const float* b1   = (const float*)d_in[5];
    const float* Wr1  = (const float*)d_in[6];
    const float* br1  = (const float*)d_in[7];
    const float* W2   = (const float*)d_in[8];
    const float* b2   = (const float*)d_in[9];
    const float* Wr2  = (const float*)d_in[10];
    const float* br2  = (const float*)d_in[11];
    float* out = (float*)d_out;

    void *pH, *pT, *pWc2, *pBc2;
    cudaGetSymbolAddress(&pH, g_h);
    cudaGetSymbolAddress(&pT, g_T);
    cudaGetSymbolAddress(&pWc2, g_Wc2);
    cudaGetSymbolAddress(&pBc2, g_bc2);

    static bool attr_set = false;
    if (!attr_set) {
        cudaFuncSetAttribute(gemm1_mma, cudaFuncAttributeMaxDynamicSharedMemorySize, GEMM1_SMEM);
        attr_set = true;
    }

    // 1. pack (Bt hi/lo, Wc2, biases, zero hist)
    pack_kernel<<<512, 256>>>(W1, Wr1, br1, W2, Wr2, br2);
    // 2. convert x -> bf16 hi/lo
    convertA_kernel<<<(N_NODES * (NFEAT / 8) + 255) / 256, 256>>>(x);
    // 3. histogram (independent of GEMM)
    hist_kernel<<<(N_EDGES + 255) / 256, 256>>>(edst);
    // 4. GEMM1: S = x @ [W1|Wr1] + [0|br1]  (HMMA bf16 3-term, 2 CTA/SM)
    {
        dim3 grid((N_NODES + 127) / 128, 2);
        gemm1_mma<<<grid, 256, GEMM1_SMEM>>>();
    }
    // 5-6. CSR scan + scatter
    scan_kernel<<<1, 1024>>>();
    scatter_kernel<<<(N_EDGES + 255) / 256, 256>>>(esrc, edst, eval_);
    // 7. h = [relu(b1 + spmm(S[:,:128])) | S[:,128:]]
    spmm1_csr<<<(N_NODES + 7) / 8, 256>>>(b1);
    // 8. T = h @ [W2|Wr2] (+[0|br2])
    sgemm_n80<<<(N_NODES + 127) / 128, 256>>>((const float*)pH, (const float*)pWc2,
                                              (const float*)pBc2, (float*)pT,
                                              N_NODES, 256);
    // 9. out = log_softmax(b2 + spmm(T[:,:40]) + T[:,40:])
    spmm2_final<<<(N_NODES + 7) / 8, 256>>>(b2, out);
}

// round 7
// speedup vs baseline: 2.5221x; 1.1028x over previous
#include <cuda_runtime.h>
#include <cuda_bf16.h>
#include <math.h>
#include <stdint.h>

#define N_NODES 50000
#define N_EDGES 800000
#define NFEAT 512
#define NHID 128
#define NCLASS 40

// ---- scratch (static device arrays; no allocation allowed) ----
__device__ float g_S[(size_t)N_NODES * 256];     // [xW1 | xWr1+br1]
__device__ float g_T[(size_t)N_NODES * 80];      // [hW2 | hWr2+br2]
__device__ float g_bc1[256];                     // [0 | br1]
__device__ float g_bc2[80];                      // [0 | br2]
// CSR-by-destination build
__device__ int   g_counts[N_NODES];
__device__ int   g_row_start[N_NODES + 1];
__device__ int   g_cursor[N_NODES];
__device__ int   g_es[N_EDGES];
__device__ float g_ev[N_EDGES];
// bf16 split operands for HMMA GEMM1
__device__ __align__(16) __nv_bfloat16 g_Ah[(size_t)N_NODES * NFEAT];
__device__ __align__(16) __nv_bfloat16 g_Al[(size_t)N_NODES * NFEAT];
__device__ __align__(16) __nv_bfloat16 g_Bth[256 * NFEAT];   // [n][k] W1|Wr1 hi
__device__ __align__(16) __nv_bfloat16 g_Btl[256 * NFEAT];   // lo
// bf16 split operands for HMMA GEMM2
__device__ __align__(16) __nv_bfloat16 g_Hh[(size_t)N_NODES * 256];  // h hi
__device__ __align__(16) __nv_bfloat16 g_Hl[(size_t)N_NODES * 256];  // h lo
__device__ __align__(16) __nv_bfloat16 g_W2th[80 * 256];     // [n][k] W2|Wr2 hi
__device__ __align__(16) __nv_bfloat16 g_W2tl[80 * 256];     // lo

// ================= helpers =================
__device__ __forceinline__ uint32_t smem_u32(const void* p) {
    uint32_t a;
    asm("{ .reg .u64 t; cvta.to.shared.u64 t, %1; cvt.u32.u64 %0, t; }" : "=r"(a) : "l"(p));
    return a;
}
#define CP_ASYNC16(dst, src) \
    asm volatile("cp.async.cg.shared.global [%0], [%1], 16;" :: "r"(dst), "l"(src) : "memory")
#define CP_COMMIT() asm volatile("cp.async.commit_group;" ::: "memory")
#define CP_WAIT(n)  asm volatile("cp.async.wait_group %0;" :: "n"(n) : "memory")

__device__ __forceinline__ void ldmx4(uint32_t addr, uint32_t& r0, uint32_t& r1,
                                      uint32_t& r2, uint32_t& r3) {
    asm volatile("ldmatrix.sync.aligned.m8n8.x4.shared.b16 {%0,%1,%2,%3}, [%4];"
                 : "=r"(r0), "=r"(r1), "=r"(r2), "=r"(r3) : "r"(addr));
}
__device__ __forceinline__ void ldmx2(uint32_t addr, uint32_t& r0, uint32_t& r1) {
    asm volatile("ldmatrix.sync.aligned.m8n8.x2.shared.b16 {%0,%1}, [%2];"
                 : "=r"(r0), "=r"(r1) : "r"(addr));
}
__device__ __forceinline__ void mma16816(float& c0, float& c1, float& c2, float& c3,
                                         uint32_t a0, uint32_t a1, uint32_t a2, uint32_t a3,
                                         uint32_t b0, uint32_t b1) {
    asm volatile("mma.sync.aligned.m16n8k16.row.col.f32.bf16.bf16.f32 "
                 "{%0,%1,%2,%3}, {%4,%5,%6,%7}, {%8,%9}, {%0,%1,%2,%3};"
                 : "+f"(c0), "+f"(c1), "+f"(c2), "+f"(c3)
                 : "r"(a0), "r"(a1), "r"(a2), "r"(a3), "r"(b0), "r"(b1));
}
// split float4 -> 4 hi bf16 (uint2) + 4 lo bf16 (uint2)
__device__ __forceinline__ void split4(float4 f, uint2& hi, uint2& lo) {
    __nv_bfloat16 h0 = __float2bfloat16(f.x), h1 = __float2bfloat16(f.y);
    __nv_bfloat16 h2 = __float2bfloat16(f.z), h3 = __float2bfloat16(f.w);
    __nv_bfloat16 l0 = __float2bfloat16(f.x - __bfloat162float(h0));
    __nv_bfloat16 l1 = __float2bfloat16(f.y - __bfloat162float(h1));
    __nv_bfloat16 l2 = __float2bfloat16(f.z - __bfloat162float(h2));
    __nv_bfloat16 l3 = __float2bfloat16(f.w - __bfloat162float(h3));
    union { __nv_bfloat162 b; uint32_t u; } p;
    p.b.x = h0; p.b.y = h1; hi.x = p.u;
    p.b.x = h2; p.b.y = h3; hi.y = p.u;
    p.b.x = l0; p.b.y = l1; lo.x = p.u;
    p.b.x = l2; p.b.y = l3; lo.y = p.u;
}

// ---- pack: B1t hi/lo, W2t hi/lo, biases, zero hist ----
__global__ void pack_kernel(const float* __restrict__ W1, const float* __restrict__ Wr1,
                            const float* __restrict__ br1,
                            const float* __restrict__ W2, const float* __restrict__ Wr2,
                            const float* __restrict__ br2) {
    int idx = blockIdx.x * blockDim.x + threadIdx.x;
    if (idx < NFEAT * 256) {
        int k = idx >> 8, n = idx & 255;
        float w = (n < 128) ? W1[k * 128 + n] : Wr1[k * 128 + (n - 128)];
        __nv_bfloat16 hi = __float2bfloat16(w);
        __nv_bfloat16 lo = __float2bfloat16(w - __bfloat162float(hi));
        g_Bth[(size_t)n * NFEAT + k] = hi;
        g_Btl[(size_t)n * NFEAT + k] = lo;
    }
    if (idx < 256 * 80) {
        int k = idx / 80, j = idx % 80;
        float w = (j < 40) ? W2[k * 40 + j] : Wr2[k * 40 + (j - 40)];
        __nv_bfloat16 hi = __float2bfloat16(w);
        __nv_bfloat16 lo = __float2bfloat16(w - __bfloat162float(hi));
        g_W2th[j * 256 + k] = hi;
        g_W2tl[j * 256 + k] = lo;
    }
    if (idx < 256) g_bc1[idx] = (idx < 128) ? 0.f : br1[idx - 128];
    if (idx < 80)  g_bc2[idx] = (idx < 40) ? 0.f : br2[idx - 40];
    if (idx < N_NODES) g_counts[idx] = 0;
}

// ---- convert x -> Ah, Al (bf16 hi/lo), row-major ----
__global__ void convertA_kernel(const float* __restrict__ x) {
    int gid = blockIdx.x * blockDim.x + threadIdx.x;  // 8 fp32 per thread
    if (gid >= N_NODES * (NFEAT / 8)) return;
    const float4* p = (const float4*)&x[(size_t)gid * 8];
    uint2 h0, l0, h1, l1;
    split4(p[0], h0, l0);
    split4(p[1], h1, l1);
    *(uint4*)&g_Ah[(size_t)gid * 8] = make_uint4(h0.x, h0.y, h1.x, h1.y);
    *(uint4*)&g_Al[(size_t)gid * 8] = make_uint4(l0.x, l0.y, l1.x, l1.y);
}

// ---- GEMM1 via mma.sync bf16 3-term: g_S = x @ [W1|Wr1] + [0|br1] ----
// CTA tile 128x128x32, 8 warps (4M x 2N), warp tile 32x64. 2 CTAs/SM.
#define ARR_SZ (128 * 40 * 2)        // bytes per smem array (80B padded rows)
#define STG_SZ (4 * ARR_SZ)          // 40960
#define GEMM1_SMEM (2 * STG_SZ)      // 81920

__global__ __launch_bounds__(256, 2) void gemm1_mma() {
    extern __shared__ unsigned char smem[];
    uint32_t sb = smem_u32(smem);
    int tid = threadIdx.x, lane = tid & 31, wid = tid >> 5;
    int warp_m = wid & 3, warp_n = wid >> 2;
    int brow = blockIdx.x * 128;
    int bcol = blockIdx.y * 128;
    int grp = lane >> 3, rr = lane & 7;

    float acc[2][8][4];
#pragma unroll
    for (int i = 0; i < 2; i++)
#pragma unroll
        for (int j = 0; j < 8; j++)
#pragma unroll
            for (int q = 0; q < 4; q++) acc[i][j][q] = 0.f;

    const __nv_bfloat16* gsrc[4] = {g_Ah, g_Al, g_Bth, g_Btl};

#define LOAD_STAGE(stage, k0) do { \
    _Pragma("unroll") \
    for (int arr = 0; arr < 4; arr++) { \
        _Pragma("unroll") \
        for (int rep = 0; rep < 2; rep++) { \
            int q = tid + rep * 256; \
            int row = q >> 2, c16 = q & 3; \
            uint32_t dst = sb + (stage) * STG_SZ + arr * ARR_SZ + row * 80 + c16 * 16; \
            const __nv_bfloat16* src; \
            if (arr < 2) { \
                int rg = brow + row; if (rg >= N_NODES) rg = N_NODES - 1; \
                src = gsrc[arr] + (size_t)rg * NFEAT + (k0) + c16 * 8; \
            } else { \
                src = gsrc[arr] + (size_t)(bcol + row) * NFEAT + (k0) + c16 * 8; \
            } \
            CP_ASYNC16(dst, src); \
        } \
    } \
    CP_COMMIT(); \
} while (0)

    LOAD_STAGE(0, 0);

    int cur = 0;
    for (int s = 0; s < 16; s++) {
        if (s < 15) {
            LOAD_STAGE(1 - cur, (s + 1) * 32);
            CP_WAIT(1);
        } else {
            CP_WAIT(0);
        }
        __syncthreads();

        uint32_t base = sb + cur * STG_SZ;
#pragma unroll
        for (int k16 = 0; k16 < 32; k16 += 16) {
            uint32_t ah[2][4], al[2][4], bh[4][4], bl[4][4];
#pragma unroll
            for (int mi = 0; mi < 2; mi++) {
                uint32_t ao = base + (uint32_t)((warp_m * 32 + mi * 16 + (grp & 1) * 8 + rr) * 80
                                                + (k16 + (grp >> 1) * 8) * 2);
                ldmx4(ao + 0 * ARR_SZ, ah[mi][0], ah[mi][1], ah[mi][2], ah[mi][3]);
                ldmx4(ao + 1 * ARR_SZ, al[mi][0], al[mi][1], al[mi][2], al[mi][3]);
            }
#pragma unroll
            for (int p = 0; p < 4; p++) {
                uint32_t bo = base + (uint32_t)((warp_n * 64 + p * 16 + (grp >> 1) * 8 + rr) * 80
                                                + (k16 + (grp & 1) * 8) * 2);
                ldmx4(bo + 2 * ARR_SZ, bh[p][0], bh[p][1], bh[p][2], bh[p][3]);
                ldmx4(bo + 3 * ARR_SZ, bl[p][0], bl[p][1], bl[p][2], bl[p][3]);
            }
#pragma unroll
            for (int mi = 0; mi < 2; mi++) {
#pragma unroll
                for (int ni = 0; ni < 8; ni++) {
                    uint32_t b0h = bh[ni >> 1][(ni & 1) * 2], b1h = bh[ni >> 1][(ni & 1) * 2 + 1];
                    uint32_t b0l = bl[ni >> 1][(ni & 1) * 2], b1l = bl[ni >> 1][(ni & 1) * 2 + 1];
                    float* c = acc[mi][ni];
                    mma16816(c[0], c[1], c[2], c[3],
                             ah[mi][0], ah[mi][1], ah[mi][2], ah[mi][3], b0h, b1h);
                    mma16816(c[0], c[1], c[2], c[3],
                             ah[mi][0], ah[mi][1], ah[mi][2], ah[mi][3], b0l, b1l);
                    mma16816(c[0], c[1], c[2], c[3],
                             al[mi][0], al[mi][1], al[mi][2], al[mi][3], b0h, b1h);
                }
            }
        }
        __syncthreads();
        cur ^= 1;
    }

#pragma unroll
    for (int mi = 0; mi < 2; mi++) {
        int r0 = brow + warp_m * 32 + mi * 16 + (lane >> 2);
#pragma unroll
        for (int ni = 0; ni < 8; ni++) {
            int c = bcol + warp_n * 64 + ni * 8 + (lane & 3) * 2;
            float bx = g_bc1[c], by = g_bc1[c + 1];
            float* cc = acc[mi][ni];
            if (r0 < N_NODES)
                *(float2*)&g_S[(size_t)r0 * 256 + c] = make_float2(cc[0] + bx, cc[1] + by);
            if (r0 + 8 < N_NODES)
                *(float2*)&g_S[(size_t)(r0 + 8) * 256 + c] = make_float2(cc[2] + bx, cc[3] + by);
        }
    }
}

// ---- GEMM2 via mma.sync bf16 3-term: g_T = h @ [W2|Wr2] + [0|br2] ----
// CTA tile 128x80x32, 8 warps (4M x 2N), warp tile 32x40 (2 m16 x 5 n8).
#define A2_SZ (128 * 80)             // 10240 bytes (hi or lo)
#define B2_SZ (80 * 80)              // 6400 bytes
#define STG2_SZ (2 * A2_SZ + 2 * B2_SZ)  // 33280
#define G2_BOFF (2 * A2_SZ)
#define GEMM2_SMEM (2 * STG2_SZ)     // 66560

__global__ __launch_bounds__(256, 2) void gemm2_mma() {
    extern __shared__ unsigned char smem[];
    uint32_t sb = smem_u32(smem);
    int tid = threadIdx.x, lane = tid & 31, wid = tid >> 5;
    int warp_m = wid & 3, warp_n = wid >> 2;
    int brow = blockIdx.x * 128;
    int grp = lane >> 3, rr = lane & 7;

    float acc[2][5][4];
#pragma unroll
    for (int i = 0; i < 2; i++)
#pragma unroll
        for (int j = 0; j < 5; j++)
#pragma unroll
            for (int q = 0; q < 4; q++) acc[i][j][q] = 0.f;

#define LOAD_STAGE2(stage, k0) do { \
    _Pragma("unroll") \
    for (int arr = 0; arr < 2; arr++) { \
        _Pragma("unroll") \
        for (int rep = 0; rep < 2; rep++) { \
            int q = tid + rep * 256; \
            int row = q >> 2, c16 = q & 3; \
            int rg = brow + row; if (rg >= N_NODES) rg = N_NODES - 1; \
            uint32_t dst = sb + (stage) * STG2_SZ + arr * A2_SZ + row * 80 + c16 * 16; \
            const __nv_bfloat16* src = (arr ? g_Hl : g_Hh) + (size_t)rg * 256 + (k0) + c16 * 8; \
            CP_ASYNC16(dst, src); \
        } \
    } \
    _Pragma("unroll") \
    for (int arr = 0; arr < 2; arr++) { \
        _Pragma("unroll") \
        for (int rep = 0; rep < 2; rep++) { \
            int q = tid + rep * 256; \
            if (q < 320) { \
                int row = q >> 2, c16 = q & 3; \
                uint32_t dst = sb + (stage) * STG2_SZ + G2_BOFF + arr * B2_SZ + row * 80 + c16 * 16; \
                const __nv_bfloat16* src = (arr ? g_W2tl : g_W2th) + row * 256 + (k0) + c16 * 8; \
                CP_ASYNC16(dst, src); \
            } \
        } \
    } \
    CP_COMMIT(); \
} while (0)

    LOAD_STAGE2(0, 0);

    int cur = 0;
    for (int s = 0; s < 8; s++) {
        if (s < 7) {
            LOAD_STAGE2(1 - cur, (s + 1) * 32);
            CP_WAIT(1);
        } else {
            CP_WAIT(0);
        }
        __syncthreads();

        uint32_t base = sb + cur * STG2_SZ;
#pragma unroll
        for (int k16 = 0; k16 < 32; k16 += 16) {
            uint32_t ah[2][4], al[2][4], bh[2][4], bl[2][4], bhx[2], blx[2];
#pragma unroll
            for (int mi = 0; mi < 2; mi++) {
                uint32_t ao = base + (uint32_t)((warp_m * 32 + mi * 16 + (grp & 1) * 8 + rr) * 80
                                                + (k16 + (grp >> 1) * 8) * 2);
                ldmx4(ao + 0 * A2_SZ, ah[mi][0], ah[mi][1], ah[mi][2], ah[mi][3]);
                ldmx4(ao + 1 * A2_SZ, al[mi][0], al[mi][1], al[mi][2], al[mi][3]);
            }
#pragma unroll
            for (int p = 0; p < 2; p++) {
                uint32_t bo = base + G2_BOFF
                            + (uint32_t)((warp_n * 40 + p * 16 + (grp >> 1) * 8 + rr) * 80
                                         + (k16 + (grp & 1) * 8) * 2);
                ldmx4(bo + 0 * B2_SZ, bh[p][0], bh[p][1], bh[p][2], bh[p][3]);
                ldmx4(bo + 1 * B2_SZ, bl[p][0], bl[p][1], bl[p][2], bl[p][3]);
            }
            {
                // last n8 tile: rows warp_n*40+32..39, 2 k8 halves via x2
                uint32_t bo = base + G2_BOFF
                            + (uint32_t)((warp_n * 40 + 32 + rr) * 80
                                         + (k16 + (grp & 1) * 8) * 2);
                ldmx2(bo + 0 * B2_SZ, bhx[0], bhx[1]);
                ldmx2(bo + 1 * B2_SZ, blx[0], blx[1]);
            }
#pragma unroll
            for (int mi = 0; mi < 2; mi++) {
#pragma unroll
                for (int ni = 0; ni < 5; ni++) {
                    uint32_t b0h, b1h, b0l, b1l;
                    if (ni < 4) {
                        b0h = bh[ni >> 1][(ni & 1) * 2]; b1h = bh[ni >> 1][(ni & 1) * 2 + 1];
                        b0l = bl[ni >> 1][(ni & 1) * 2]; b1l = bl[ni >> 1][(ni & 1) * 2 + 1];
                    } else {
                        b0h = bhx[0]; b1h = bhx[1];
                        b0l = blx[0]; b1l = blx[1];
                    }
                    float* c = acc[mi][ni];
                    mma16816(c[0], c[1], c[2], c[3],
                             ah[mi][0], ah[mi][1], ah[mi][2], ah[mi][3], b0h, b1h);
                    mma16816(c[0], c[1], c[2], c[3],
                             ah[mi][0], ah[mi][1], ah[mi][2], ah[mi][3], b0l, b1l);
                    mma16816(c[0], c[1], c[2], c[3],
                             al[mi][0], al[mi][1], al[mi][2], al[mi][3], b0h, b1h);
                }
            }
        }
        __syncthreads();
        cur ^= 1;
    }

#pragma unroll
    for (int mi = 0; mi < 2; mi++) {
        int r0 = brow + warp_m * 32 + mi * 16 + (lane >> 2);
#pragma unroll
        for (int ni = 0; ni < 5; ni++) {
            int c = warp_n * 40 + ni * 8 + (lane & 3) * 2;
            float bx = g_bc2[c], by = g_bc2[c + 1];
            float* cc = acc[mi][ni];
            if (r0 < N_NODES)
                *(float2*)&g_T[(size_t)r0 * 80 + c] = make_float2(cc[0] + bx, cc[1] + by);
            if (r0 + 8 < N_NODES)
                *(float2*)&g_T[(size_t)(r0 + 8) * 80 + c] = make_float2(cc[2] + bx, cc[3] + by);
        }
    }
}

// ---- histogram / scan / scatter (CSR build) ----
__global__ void hist_kernel(const int* __restrict__ dst) {
    int e = blockIdx.x * blockDim.x + threadIdx.x;
    if (e < N_EDGES) atomicAdd(&g_counts[dst[e]], 1);
}

// single-block shuffle-based scan
__global__ void scan_kernel() {
    __shared__ int wsum[32];
    __shared__ int chunk_total;
    int tid = threadIdx.x, lane = tid & 31, w = tid >> 5;
    int offset = 0;
    for (int base = 0; base < N_NODES; base += 1024) {
        int i = base + tid;
        int c = (i < N_NODES) ? g_counts[i] : 0;
        int v = c;
#pragma unroll
        for (int d = 1; d < 32; d <<= 1) {
            int t = __shfl_up_sync(0xffffffffu, v, d);
            if (lane >= d) v += t;
        }
        if (lane == 31) wsum[w] = v;
        __syncthreads();
        if (w == 0) {
            int s = wsum[lane];
#pragma unroll
            for (int d = 1; d < 32; d <<= 1) {
                int t = __shfl_up_sync(0xffffffffu, s, d);
                if (lane >= d) s += t;
            }
            wsum[lane] = s;
            if (lane == 31) chunk_total = s;
        }
        __syncthreads();
        int warp_prefix = (w == 0) ? 0 : wsum[w - 1];
        int excl = v - c + warp_prefix + offset;
        if (i < N_NODES) {
            g_row_start[i] = excl;
            g_cursor[i] = excl;
        }
        offset += chunk_total;
        __syncthreads();
    }
    if (tid == 0) g_row_start[N_NODES] = offset;
}

__global__ void scatter_kernel(const int* __restrict__ src, const int* __restrict__ dst,
                               const float* __restrict__ val) {
    int e = blockIdx.x * blockDim.x + threadIdx.x;
    if (e >= N_EDGES) return;
    int d = dst[e];
    int p = atomicAdd(&g_cursor[d], 1);
    g_es[p] = src[e];
    g_ev[p] = val[e];
}

// ---- SpMM1 (CSR, warp per dst row, 4-edge unroll): writes bf16 hi/lo h ----
__global__ void spmm1_csr(const float* __restrict__ b1) {
    int w = (blockIdx.x * blockDim.x + threadIdx.x) >> 5;
    int lane = threadIdx.x & 31;
    if (w >= N_NODES) return;
    int e = g_row_start[w];
    int end = g_row_start[w + 1];
    float4 acc = *(const float4*)&b1[lane * 4];
    for (; e + 4 <= end; e += 4) {
        int s0 = g_es[e], s1 = g_es[e + 1], s2 = g_es[e + 2], s3 = g_es[e + 3];
        float v0 = g_ev[e], v1 = g_ev[e + 1], v2 = g_ev[e + 2], v3 = g_ev[e + 3];
        float4 x0 = *(const float4*)&g_S[(size_t)s0 * 256 + lane * 4];
        float4 x1 = *(const float4*)&g_S[(size_t)s1 * 256 + lane * 4];
        float4 x2 = *(const float4*)&g_S[(size_t)s2 * 256 + lane * 4];
        float4 x3 = *(const float4*)&g_S[(size_t)s3 * 256 + lane * 4];
        acc.x = fmaf(v0, x0.x, acc.x); acc.y = fmaf(v0, x0.y, acc.y);
        acc.z = fmaf(v0, x0.z, acc.z); acc.w = fmaf(v0, x0.w, acc.w);
        acc.x = fmaf(v1, x1.x, acc.x); acc.y = fmaf(v1, x1.y, acc.y);
        acc.z = fmaf(v1, x1.z, acc.z); acc.w = fmaf(v1, x1.w, acc.w);
        acc.x = fmaf(v2, x2.x, acc.x); acc.y = fmaf(v2, x2.y, acc.y);
        acc.z = fmaf(v2, x2.z, acc.z); acc.w = fmaf(v2, x2.w, acc.w);
        acc.x = fmaf(v3, x3.x, acc.x); acc.y = fmaf(v3, x3.y, acc.y);
        acc.z = fmaf(v3, x3.z, acc.z); acc.w = fmaf(v3, x3.w, acc.w);
    }
    for (; e < end; e++) {
        int s0 = g_es[e];
        float v0 = g_ev[e];
        float4 x0 = *(const float4*)&g_S[(size_t)s0 * 256 + lane * 4];
        acc.x = fmaf(v0, x0.x, acc.x); acc.y = fmaf(v0, x0.y, acc.y);
        acc.z = fmaf(v0, x0.z, acc.z); acc.w = fmaf(v0, x0.w, acc.w);
    }
    float4 o;
    o.x = fmaxf(acc.x, 0.f); o.y = fmaxf(acc.y, 0.f);
    o.z = fmaxf(acc.z, 0.f); o.w = fmaxf(acc.w, 0.f);
    uint2 hi, lo;
    split4(o, hi, lo);
    *(uint2*)&g_Hh[(size_t)w * 256 + lane * 4] = hi;
    *(uint2*)&g_Hl[(size_t)w * 256 + lane * 4] = lo;
    float4 r = *(const float4*)&g_S[(size_t)w * 256 + 128 + lane * 4];
    split4(r, hi, lo);
    *(uint2*)&g_Hh[(size_t)w * 256 + 128 + lane * 4] = hi;
    *(uint2*)&g_Hl[(size_t)w * 256 + 128 + lane * 4] = lo;
}

// ---- SpMM2 (CSR, warp per dst row, 4-edge unroll) fused final -> out ----
__global__ void spmm2_final(const float* __restrict__ b2, float* __restrict__ out) {
    int w = (blockIdx.x * blockDim.x + threadIdx.x) >> 5;
    int lane = threadIdx.x & 31;
    if (w >= N_NODES) return;
    int e = g_row_start[w];
    int end = g_row_start[w + 1];
    bool act = lane < 20;
    float ax = 0.f, ay = 0.f;
    if (act) { ax = b2[2 * lane]; ay = b2[2 * lane + 1]; }
    for (; e + 4 <= end; e += 4) {
        int s0 = g_es[e], s1 = g_es[e + 1], s2 = g_es[e + 2], s3 = g_es[e + 3];
        float v0 = g_ev[e], v1 = g_ev[e + 1], v2 = g_ev[e + 2], v3 = g_ev[e + 3];
        if (act) {
            float2 t0 = *(const float2*)&g_T[(size_t)s0 * 80 + 2 * lane];
            float2 t1 = *(const float2*)&g_T[(size_t)s1 * 80 + 2 * lane];
            float2 t2 = *(const float2*)&g_T[(size_t)s2 * 80 + 2 * lane];
            float2 t3 = *(const float2*)&g_T[(size_t)s3 * 80 + 2 * lane];
            ax = fmaf(v0, t0.x, ax); ay = fmaf(v0, t0.y, ay);
            ax = fmaf(v1, t1.x, ax); ay = fmaf(v1, t1.y, ay);
            ax = fmaf(v2, t2.x, ax); ay = fmaf(v2, t2.y, ay);
            ax = fmaf(v3, t3.x, ax); ay = fmaf(v3, t3.y, ay);
        }
    }
    for (; e < end; e++) {
        int s0 = g_es[e];
        float v0 = g_ev[e];
        if (act) {
            float2 t0 = *(const float2*)&g_T[(size_t)s0 * 80 + 2 * lane];
            ax = fmaf(v0, t0.x, ax); ay = fmaf(v0, t0.y, ay);
        }
    }
    if (act) {
        float2 r = *(const float2*)&g_T[(size_t)w * 80 + 40 + 2 * lane];
        ax += r.x; ay += r.y;
    }
    float m = act ? fmaxf(ax, ay) : -INFINITY;
#pragma unroll
    for (int o = 16; o > 0; o >>= 1) m = fmaxf(m, __shfl_xor_sync(0xffffffffu, m, o));
    float s = act ? (__expf(ax - m) + __expf(ay - m)) : 0.f;
#pragma unroll
    for (int o = 16; o > 0; o >>= 1) s += __shfl_xor_sync(0xffffffffu, s, o);
    float lse = m + logf(s);
    if (act) {
        out[(size_t)w * 40 + 2 * lane + 0] = ax - lse;
        out[(size_t)w * 40 + 2 * lane + 1] = ay - lse;
    }
}

extern "C" void kernel_launch(void* const* d_in, const int* in_sizes, int n_in,
                              void* d_out, int out_size) {
    const float* x    = (const float*)d_in[0];
    const int*   esrc = (const int*)d_in[1];
    const int*   edst = (const int*)d_in[2];
    const float* eval_= (const float*)d_in[3];
    const float* W1   = (const float*)d_in[4];
    const float* b1   = (const float*)d_in[5];
    const float* Wr1  = (const float*)d_in[6];
    const float* br1  = (const float*)d_in[7];
    const float* W2   = (const float*)d_in[8];
    const float* b2   = (const float*)d_in[9];
    const float* Wr2  = (const float*)d_in[10];
    const float* br2  = (const float*)d_in[11];
    float* out = (float*)d_out;

    static bool attr_set = false;
    if (!attr_set) {
        cudaFuncSetAttribute(gemm1_mma, cudaFuncAttributeMaxDynamicSharedMemorySize, GEMM1_SMEM);
        cudaFuncSetAttribute(gemm2_mma, cudaFuncAttributeMaxDynamicSharedMemorySize, GEMM2_SMEM);
        attr_set = true;
    }

    // 1. pack (B1t hi/lo, W2t hi/lo, biases, zero hist)
    pack_kernel<<<512, 256>>>(W1, Wr1, br1, W2, Wr2, br2);
    // 2. convert x -> bf16 hi/lo
    convertA_kernel<<<(N_NODES * (NFEAT / 8) + 255) / 256, 256>>>(x);
    // 3. histogram (independent of GEMM)
    hist_kernel<<<(N_EDGES + 255) / 256, 256>>>(edst);
    // 4. GEMM1: S = x @ [W1|Wr1] + [0|br1]  (HMMA bf16 3-term)
    {
        dim3 grid((N_NODES + 127) / 128, 2);
        gemm1_mma<<<grid, 256, GEMM1_SMEM>>>();
    }
    // 5-6. CSR scan + scatter
    scan_kernel<<<1, 1024>>>();
    scatter_kernel<<<(N_EDGES + 255) / 256, 256>>>(esrc, edst, eval_);
    // 7. h(bf16 hi/lo) = [relu(b1 + spmm(S[:,:128])) | S[:,128:]]
    spmm1_csr<<<(N_NODES + 7) / 8, 256>>>(b1);
    // 8. T = h @ [W2|Wr2] + [0|br2]  (HMMA bf16 3-term)
    gemm2_mma<<<(N_NODES + 127) / 128, 256, GEMM2_SMEM>>>();
    // 9. out = log_softmax(b2 + spmm(T[:,:40]) + T[:,40:])
    spmm2_final<<<(N_NODES + 7) / 8, 256>>>(b2, out);
}